// round 8
// baseline (speedup 1.0000x reference)
#include <cuda_runtime.h>
#include <cuda_bf16.h>
#include <cstdint>

// ---------------- problem constants ----------------
#define TOTAL_BINS 28749
#define BATCH      2048
#define ROWS       4096      // BATCH * 2 channels
#define INPUT_DIM  2200      // 22 * 50 * 2
#define H1_DIM     1000
#define H2_DIM     50
#define OUT_DIM    13
#define N_HEADS    22
#define COMP       50

__device__ __constant__ int d_LOC[23] = {
    0, 2490, 4912, 6895, 8797, 10612, 12320, 13913, 15364, 16748, 18086,
    19437, 20770, 21914, 22984, 24004, 24907, 25740, 26544, 27130, 27774,
    28241, 28749};

// ---------------- scratch (no allocations allowed) ----------------
__device__ float g_combined[BATCH * INPUT_DIM];
__device__ float g_z[BATCH * INPUT_DIM];
__device__ float g_h1[BATCH * H1_DIM];
__device__ float g_w2t[H1_DIM * H2_DIM];

// ---------------- smem layout (dynamic), bf16 tiles, pitch 72 bf16 ----
#define PITCH_B   144        // 72 bf16 * 2 bytes
#define OFF_AH    0          // 128 x 72 bf16 = 18432 B
#define OFF_AL    18432
#define OFF_WH    36864      // 64 x 72 bf16 = 9216 B
#define OFF_WL    46080
#define SMEM_TOTAL 55296

__device__ __forceinline__ uint32_t su32(const void* p) {
    uint32_t a;
    asm("{ .reg .u64 t; cvta.to.shared.u64 t, %1; cvt.u32.u64 %0, t; }"
        : "=r"(a) : "l"(p));
    return a;
}

#define LDSM4(r0, r1, r2, r3, addr)                                          \
    asm volatile(                                                            \
        "ldmatrix.sync.aligned.m8n8.x4.shared.b16 {%0,%1,%2,%3}, [%4];"      \
        : "=r"(r0), "=r"(r1), "=r"(r2), "=r"(r3) : "r"(addr))

__device__ __forceinline__ void mma_bf16(float* d, const uint32_t* a,
                                         uint32_t b0, uint32_t b1) {
    asm volatile(
        "mma.sync.aligned.m16n8k16.row.col.f32.bf16.bf16.f32 "
        "{%0,%1,%2,%3}, {%4,%5,%6,%7}, {%8,%9}, {%0,%1,%2,%3};"
        : "+f"(d[0]), "+f"(d[1]), "+f"(d[2]), "+f"(d[3])
        : "r"(a[0]), "r"(a[1]), "r"(a[2]), "r"(a[3]), "r"(b0), "r"(b1));
}

__device__ __forceinline__ void split_pack(float v0, float v1, uint32_t& hp,
                                           uint32_t& lp) {
    const __nv_bfloat16 h0 = __float2bfloat16(v0);
    const __nv_bfloat16 h1 = __float2bfloat16(v1);
    const __nv_bfloat16 l0 = __float2bfloat16(v0 - __bfloat162float(h0));
    const __nv_bfloat16 l1 = __float2bfloat16(v1 - __bfloat162float(h1));
    hp = ((uint32_t)__bfloat16_as_ushort(h1) << 16) | __bfloat16_as_ushort(h0);
    lp = ((uint32_t)__bfloat16_as_ushort(l1) << 16) | __bfloat16_as_ushort(l0);
}

// =====================================================================
// Tensor-core GEMM via mma.sync, bf16 hi/lo split (3 products):
//   C[M,N] = A[M,K] @ W[N,K]^T + bias  (opt leaky)
// EPI: 0 = plain, 1 = leaky, 2 = heads (segmented K, scatter output)
// Block: 256 thr (8 warps, 4x2), tile M=128 x N=64, K-chunk 64.
// =====================================================================
template <int EPI>
__global__ __launch_bounds__(256) void k_mma(
    const float* __restrict__ Ain, int lda, const float* __restrict__ Win,
    int ldw, const float* __restrict__ bias_in, float* __restrict__ C,
    int ldc, int Nin, int Kin) {
    extern __shared__ __align__(16) char smem[];
    const uint32_t sb = su32(smem);
    const int tid = threadIdx.x;
    const int lane = tid & 31, wid = tid >> 5;
    const int wm = wid & 3, wn = wid >> 2;   // warp 32-row group, 32-col group
    const int m0 = blockIdx.x * 128;

    const float* A = Ain;
    const float* W = Win;
    const float* bias = bias_in;
    int N = Nin, K = Kin, n0 = 0, seg = 0;
    if (EPI == 2) {
        seg = blockIdx.y;
        const int a = d_LOC[seg];
        K = d_LOC[seg + 1] - a;
        A = Ain + a;
        W = Win + a;
        bias = bias_in + seg * COMP;
        N = COMP;
    } else {
        n0 = blockIdx.y * 64;
    }
    const int nv = (N - n0 < 64) ? (N - n0) : 64;  // valid cols in this tile

    float acc[2][4][4];
#pragma unroll
    for (int mt = 0; mt < 2; mt++)
#pragma unroll
        for (int nt = 0; nt < 4; nt++)
#pragma unroll
            for (int q = 0; q < 4; q++) acc[mt][nt][q] = 0.f;

    // per-thread ldmatrix smem addresses (byte offsets fixed across chunks)
    // A frag (m8n8.x4 over 16x16): lanes 0-15 -> rows 0..15, lanes 16-31 -> +8 cols
    const uint32_t a_row = (uint32_t)(wm * 32 + (lane & 15));
    const uint32_t a_cb  = (uint32_t)((lane >> 4) << 4);      // +16 B for k+8
    // W frag (x4 over two 8-row n-tiles x 16 k)
    const uint32_t w_row = (uint32_t)(wn * 32 + ((lane >> 4) << 3) + (lane & 7));
    const uint32_t w_cb  = (uint32_t)((lane & 8) * 2);        // +16 B for k+8

    const int nch = (K + 63) >> 6;
    for (int ch = 0; ch < nch; ch++) {
        const int k0 = ch << 6;
        if (ch) __syncthreads();   // protect smem from previous iteration's reads

        // ---- load + convert A tile: 128 rows x 32 bf16x2 pairs ----
#pragma unroll
        for (int i = 0; i < 16; i++) {
            const int idx = i * 256 + tid;
            const int row = idx >> 5, kp = idx & 31;
            const int k = k0 + kp * 2;
            const float* ap = A + (size_t)(m0 + row) * lda + k;
            const float v0 = (k < K) ? ap[0] : 0.f;
            const float v1 = (k + 1 < K) ? ap[1] : 0.f;
            uint32_t hp, lp;
            split_pack(v0, v1, hp, lp);
            const uint32_t o = row * PITCH_B + kp * 4;
            *(uint32_t*)(smem + OFF_AH + o) = hp;
            *(uint32_t*)(smem + OFF_AL + o) = lp;
        }
        // ---- load + convert W tile: 64 rows x 32 pairs ----
#pragma unroll
        for (int i = 0; i < 8; i++) {
            const int idx = i * 256 + tid;
            const int row = idx >> 5, kp = idx & 31;
            const int k = k0 + kp * 2;
            const bool rv = row < nv;
            const float* wp = W + (size_t)(n0 + row) * ldw + k;
            const float v0 = (rv && k < K) ? wp[0] : 0.f;
            const float v1 = (rv && k + 1 < K) ? wp[1] : 0.f;
            uint32_t hp, lp;
            split_pack(v0, v1, hp, lp);
            const uint32_t o = row * PITCH_B + kp * 4;
            *(uint32_t*)(smem + OFF_WH + o) = hp;
            *(uint32_t*)(smem + OFF_WL + o) = lp;
        }
        __syncthreads();

#pragma unroll
        for (int ks = 0; ks < 4; ks++) {
            const uint32_t acb = ks * 32 + a_cb;
            const uint32_t wcb = ks * 32 + w_cb;
            uint32_t ah[2][4], al[2][4], wh[4][2], wl[4][2];
#pragma unroll
            for (int mt = 0; mt < 2; mt++) {
                const uint32_t ro = (a_row + mt * 16) * PITCH_B + acb;
                LDSM4(ah[mt][0], ah[mt][1], ah[mt][2], ah[mt][3],
                      sb + OFF_AH + ro);
                LDSM4(al[mt][0], al[mt][1], al[mt][2], al[mt][3],
                      sb + OFF_AL + ro);
            }
#pragma unroll
            for (int p = 0; p < 2; p++) {
                const uint32_t ro = (w_row + p * 16) * PITCH_B + wcb;
                LDSM4(wh[2 * p][0], wh[2 * p][1], wh[2 * p + 1][0],
                      wh[2 * p + 1][1], sb + OFF_WH + ro);
                LDSM4(wl[2 * p][0], wl[2 * p][1], wl[2 * p + 1][0],
                      wl[2 * p + 1][1], sb + OFF_WL + ro);
            }
#pragma unroll
            for (int mt = 0; mt < 2; mt++)
#pragma unroll
                for (int nt = 0; nt < 4; nt++) {
                    mma_bf16(acc[mt][nt], ah[mt], wh[nt][0], wh[nt][1]);
                    mma_bf16(acc[mt][nt], ah[mt], wl[nt][0], wl[nt][1]);
                    mma_bf16(acc[mt][nt], al[mt], wh[nt][0], wh[nt][1]);
                }
        }
    }

    // ---- epilogue: registers -> global (float2 pairs, cols adjacent) ----
#pragma unroll
    for (int mt = 0; mt < 2; mt++) {
        const int rowl = wm * 32 + mt * 16 + (lane >> 2);
#pragma unroll
        for (int nt = 0; nt < 4; nt++) {
            const int col = wn * 32 + nt * 8 + 2 * (lane & 3);
            if (col >= nv) continue;
            if (EPI == 2) {
                const float b0 = bias[col], b1 = bias[col + 1];
#pragma unroll
                for (int h = 0; h < 2; h++) {
                    const int r = m0 + rowl + h * 8;
                    const int b = r >> 1, c = r & 1;
                    float2 v = {acc[mt][nt][2 * h] + b0,
                                acc[mt][nt][2 * h + 1] + b1};
                    *(float2*)(C + (size_t)b * INPUT_DIM + seg * 100 +
                               c * COMP + col) = v;
                }
            } else {
                const int n = n0 + col;
                const float b0 = bias[n], b1 = bias[n + 1];
#pragma unroll
                for (int h = 0; h < 2; h++) {
                    float v0 = acc[mt][nt][2 * h] + b0;
                    float v1 = acc[mt][nt][2 * h + 1] + b1;
                    if (EPI == 1) {
                        v0 = v0 > 0.f ? v0 : 0.01f * v0;
                        v1 = v1 > 0.f ? v1 : 0.01f * v1;
                    }
                    float2 v = {v0, v1};
                    *(float2*)(C + (size_t)(m0 + rowl + h * 8) * ldc + n) = v;
                }
            }
        }
    }
}

// transpose w2 (50 x 1000) -> w2t (1000 x 50)
__global__ void k_transpose_w2(const float* __restrict__ w2,
                               float* __restrict__ w2t) {
    int idx = blockIdx.x * 256 + threadIdx.x;
    if (idx < H2_DIM * H1_DIM) {
        int n = idx / H1_DIM, k = idx % H1_DIM;
        w2t[k * H2_DIM + n] = w2[idx];
    }
}

// fused tail: h2 = leaky(h1 @ w2^T + b2); out = h2 @ w3^T + b3
__global__ __launch_bounds__(128) void k_tail(
    const float* __restrict__ h1, const float* __restrict__ w2t,
    const float* __restrict__ b2, const float* __restrict__ w3,
    const float* __restrict__ b3, float* __restrict__ out) {
    const int m = blockIdx.x;
    __shared__ float s[H1_DIM];
    __shared__ float s2[H2_DIM];
    const int tid = threadIdx.x;

    for (int i = tid; i < H1_DIM; i += 128) s[i] = h1[(size_t)m * H1_DIM + i];
    __syncthreads();

    if (tid < H2_DIM) {
        float acc = b2[tid];
#pragma unroll 4
        for (int k = 0; k < H1_DIM; k++) acc += s[k] * w2t[k * H2_DIM + tid];
        s2[tid] = acc > 0.f ? acc : 0.01f * acc;
    }
    __syncthreads();

    if (tid < OUT_DIM) {
        float acc = b3[tid];
#pragma unroll
        for (int k = 0; k < H2_DIM; k++) acc += s2[k] * w3[tid * H2_DIM + k];
        out[(size_t)m * OUT_DIM + tid] = acc;
    }
}

// =====================================================================
extern "C" void kernel_launch(void* const* d_in, const int* in_sizes, int n_in,
                              void* d_out, int out_size) {
    const float* x      = (const float*)d_in[0];
    const float* head_w = (const float*)d_in[1];
    const float* head_b = (const float*)d_in[2];
    const float* conc_w = (const float*)d_in[3];
    const float* conc_b = (const float*)d_in[4];
    const float* w1     = (const float*)d_in[5];
    const float* b1     = (const float*)d_in[6];
    const float* w2     = (const float*)d_in[7];
    const float* b2     = (const float*)d_in[8];
    const float* w3     = (const float*)d_in[9];
    const float* b3     = (const float*)d_in[10];
    float* out = (float*)d_out;

    float *combined, *z, *h1v, *w2t;
    cudaGetSymbolAddress((void**)&combined, g_combined);
    cudaGetSymbolAddress((void**)&z, g_z);
    cudaGetSymbolAddress((void**)&h1v, g_h1);
    cudaGetSymbolAddress((void**)&w2t, g_w2t);

    cudaFuncSetAttribute(k_mma<0>, cudaFuncAttributeMaxDynamicSharedMemorySize,
                         SMEM_TOTAL);
    cudaFuncSetAttribute(k_mma<1>, cudaFuncAttributeMaxDynamicSharedMemorySize,
                         SMEM_TOTAL);
    cudaFuncSetAttribute(k_mma<2>, cudaFuncAttributeMaxDynamicSharedMemorySize,
                         SMEM_TOTAL);

    // Stage 1: 22 block-diagonal head GEMMs -> combined (2048 x 2200)
    k_mma<2><<<dim3(ROWS / 128, N_HEADS), 256, SMEM_TOTAL>>>(
        x, TOTAL_BINS, head_w, TOTAL_BINS, head_b, combined, 0, 0, 0);

    // Stage 2: z = combined @ conc_w^T + conc_b (2048 x 2200)
    k_mma<0><<<dim3(BATCH / 128, (INPUT_DIM + 63) / 64), 256, SMEM_TOTAL>>>(
        combined, INPUT_DIM, conc_w, INPUT_DIM, conc_b, z, INPUT_DIM,
        INPUT_DIM, INPUT_DIM);

    // Stage 3: h1 = leaky(z @ w1^T + b1) (2048 x 1000)
    k_mma<1><<<dim3(BATCH / 128, (H1_DIM + 63) / 64), 256, SMEM_TOTAL>>>(
        z, INPUT_DIM, w1, INPUT_DIM, b1, h1v, H1_DIM, H1_DIM, INPUT_DIM);

    // Stage 4+5 fused tail
    k_transpose_w2<<<(H1_DIM * H2_DIM + 255) / 256, 256>>>(w2, w2t);
    k_tail<<<BATCH, 128>>>(h1v, w2t, b2, w3, b3, out);
}

// round 11
// speedup vs baseline: 1.1882x; 1.1882x over previous
#include <cuda_runtime.h>
#include <cuda_bf16.h>
#include <cstdint>

// ---------------- problem constants ----------------
#define TOTAL_BINS 28749
#define BATCH      2048
#define ROWS       4096
#define INPUT_DIM  2200
#define IN_PAD     2240      // INPUT_DIM padded to 64
#define H1_DIM     1000
#define H1_PAD     1024
#define H2_DIM     50
#define OUT_DIM    13
#define N_HEADS    22
#define COMP       50
#define HW_PAD     29312     // sum of per-segment 64-padded K

__device__ __constant__ int d_LOC[23] = {
    0, 2490, 4912, 6895, 8797, 10612, 12320, 13913, 15364, 16748, 18086,
    19437, 20770, 21914, 22984, 24004, 24907, 25740, 26544, 27130, 27774,
    28241, 28749};
__device__ __constant__ int d_LOC64[23] = {
    0, 2496, 4928, 6912, 8832, 10688, 12416, 14016, 15488, 16896, 18240,
    19648, 20992, 22144, 23232, 24256, 25216, 26112, 26944, 27584, 28288,
    28800, 29312};

// ---------------- scratch (zero-initialized; pads never written) -----
__device__ __nv_bfloat16 g_hwh[64 * HW_PAD];
__device__ __nv_bfloat16 g_hwl[64 * HW_PAD];
__device__ __nv_bfloat16 g_cwh[INPUT_DIM * IN_PAD];
__device__ __nv_bfloat16 g_cwl[INPUT_DIM * IN_PAD];
__device__ __nv_bfloat16 g_w1h[H1_DIM * IN_PAD];
__device__ __nv_bfloat16 g_w1l[H1_DIM * IN_PAD];
__device__ __nv_bfloat16 g_w2h[H2_DIM * H1_PAD];
__device__ __nv_bfloat16 g_w2l[H2_DIM * H1_PAD];
__device__ __nv_bfloat16 g_ch[BATCH * IN_PAD];
__device__ __nv_bfloat16 g_cl[BATCH * IN_PAD];
__device__ __nv_bfloat16 g_zh[BATCH * IN_PAD];
__device__ __nv_bfloat16 g_zl[BATCH * IN_PAD];
__device__ __nv_bfloat16 g_h1h[BATCH * H1_PAD];
__device__ __nv_bfloat16 g_h1l[BATCH * H1_PAD];
__device__ float         g_h2[BATCH * H2_DIM];

// ---------------- smem layout, pitch 72 bf16 = 144 B -----------------
#define PITCH_B   144
#define OFF_AH    0
#define OFF_AL    18432
#define OFF_WH    36864
#define OFF_WL    46080
#define SMEM_TOTAL 55296

__device__ __forceinline__ uint32_t su32(const void* p) {
    uint32_t a;
    asm("{ .reg .u64 t; cvta.to.shared.u64 t, %1; cvt.u32.u64 %0, t; }"
        : "=r"(a) : "l"(p));
    return a;
}

#define LDSM4(r0, r1, r2, r3, addr)                                          \
    asm volatile(                                                            \
        "ldmatrix.sync.aligned.m8n8.x4.shared.b16 {%0,%1,%2,%3}, [%4];"      \
        : "=r"(r0), "=r"(r1), "=r"(r2), "=r"(r3) : "r"(addr))

__device__ __forceinline__ void mma_bf16(float* d, const uint32_t* a,
                                         uint32_t b0, uint32_t b1) {
    asm volatile(
        "mma.sync.aligned.m16n8k16.row.col.f32.bf16.bf16.f32 "
        "{%0,%1,%2,%3}, {%4,%5,%6,%7}, {%8,%9}, {%0,%1,%2,%3};"
        : "+f"(d[0]), "+f"(d[1]), "+f"(d[2]), "+f"(d[3])
        : "r"(a[0]), "r"(a[1]), "r"(a[2]), "r"(a[3]), "r"(b0), "r"(b1));
}

__device__ __forceinline__ void split_pack(float v0, float v1, uint32_t& hp,
                                           uint32_t& lp) {
    const __nv_bfloat16 h0 = __float2bfloat16(v0);
    const __nv_bfloat16 h1 = __float2bfloat16(v1);
    const __nv_bfloat16 l0 = __float2bfloat16(v0 - __bfloat162float(h0));
    const __nv_bfloat16 l1 = __float2bfloat16(v1 - __bfloat162float(h1));
    hp = ((uint32_t)__bfloat16_as_ushort(h1) << 16) | __bfloat16_as_ushort(h0);
    lp = ((uint32_t)__bfloat16_as_ushort(l1) << 16) | __bfloat16_as_ushort(l0);
}

// =====================================================================
// Weight pre-split: fp32 [N][K] -> bf16 hi/lo [N][KP] (pads stay zero)
// =====================================================================
__global__ __launch_bounds__(256) void k_cvt_pad(
    const float* __restrict__ src, __nv_bfloat16* __restrict__ dh,
    __nv_bfloat16* __restrict__ dl, int N, int K, int KP) {
    const int k4 = K >> 2;
    const int i4 = blockIdx.x * 256 + threadIdx.x;
    if (i4 >= N * k4) return;
    const int row = i4 / k4, col = (i4 - row * k4) * 4;
    const float4 v = *(const float4*)(src + (size_t)row * K + col);
    uint32_t h0, l0, h1, l1;
    split_pack(v.x, v.y, h0, l0);
    split_pack(v.z, v.w, h1, l1);
    const size_t o = (size_t)row * KP + col;
    *(uint2*)(dh + o) = make_uint2(h0, h1);
    *(uint2*)(dl + o) = make_uint2(l0, l1);
}

// head_w fp32 [50][28749] -> padded [64][HW_PAD] hi/lo (per-seg 64-aligned)
__global__ __launch_bounds__(256) void k_cvt_hw(
    const float* __restrict__ hw, __nv_bfloat16* __restrict__ dh,
    __nv_bfloat16* __restrict__ dl) {
    const int o = blockIdx.y;
    const int kp = blockIdx.x * 256 + threadIdx.x;
    if (kp >= TOTAL_BINS) return;
    int seg = 0;
#pragma unroll
    for (int s = 1; s < 22; s++) seg += (kp >= d_LOC[s]);
    const float v = hw[(size_t)o * TOTAL_BINS + kp];
    const __nv_bfloat16 h = __float2bfloat16(v);
    const size_t off = (size_t)o * HW_PAD + d_LOC64[seg] + (kp - d_LOC[seg]);
    dh[off] = h;
    dl[off] = __float2bfloat16(v - __bfloat162float(h));
}

// =====================================================================
// Heads: A = x fp32 (split in-kernel), W = padded hi/lo. 3 products.
// Tile 128 x 64(=50), K-chunk 64, 256 thr (warps 4m x 2n).
// Output: combined as bf16 hi/lo, scattered layout, row stride IN_PAD.
// =====================================================================
__global__ __launch_bounds__(256) void k_heads(
    const float* __restrict__ x, const __nv_bfloat16* __restrict__ hwh,
    const __nv_bfloat16* __restrict__ hwl, const float* __restrict__ hb,
    __nv_bfloat16* __restrict__ ch, __nv_bfloat16* __restrict__ cl) {
    extern __shared__ __align__(16) char smem[];
    const uint32_t sb = su32(smem);
    const int tid = threadIdx.x, lane = tid & 31, wid = tid >> 5;
    const int wm = wid & 3, wn = wid >> 2;
    const int m0 = blockIdx.x * 128, seg = blockIdx.y;
    const int a = d_LOC[seg], Ks = d_LOC[seg + 1] - a;
    const int kb = d_LOC64[seg];
    const int nch = (d_LOC64[seg + 1] - kb) >> 6;
    const float* bias = hb + seg * COMP;

    float acc[2][4][4] = {};
    const uint32_t a_row = (uint32_t)(wm * 32 + (lane & 15));
    const uint32_t a_cb = (uint32_t)((lane >> 4) << 4);
    const uint32_t w_row = (uint32_t)(wn * 32 + ((lane >> 4) << 3) + (lane & 7));
    const uint32_t w_cb = (uint32_t)((lane & 8) * 2);

    for (int ch_i = 0; ch_i < nch; ch_i++) {
        const int k0 = ch_i << 6;
        if (ch_i) __syncthreads();
        const bool full = (k0 + 64 <= Ks);
#pragma unroll
        for (int i = 0; i < 16; i++) {
            const int idx = i * 256 + tid;
            const int row = idx >> 5, kp = idx & 31;
            const int k = k0 + kp * 2;
            const float* ap = x + (size_t)(m0 + row) * TOTAL_BINS + a + k;
            float v0, v1;
            if (full) { v0 = ap[0]; v1 = ap[1]; }
            else {
                v0 = (k < Ks) ? ap[0] : 0.f;
                v1 = (k + 1 < Ks) ? ap[1] : 0.f;
            }
            uint32_t hp, lp;
            split_pack(v0, v1, hp, lp);
            const uint32_t o = row * PITCH_B + kp * 4;
            *(uint32_t*)(smem + OFF_AH + o) = hp;
            *(uint32_t*)(smem + OFF_AL + o) = lp;
        }
        // W: guard-free vector copy from padded buffers (rows 50..63 zero)
#pragma unroll
        for (int i = 0; i < 2; i++) {
            const int idx = i * 256 + tid;
            const int row = idx >> 3, p = idx & 7;
            const size_t so = (size_t)row * HW_PAD + kb + k0 + p * 8;
            const uint32_t o = row * PITCH_B + p * 16;
            *(uint4*)(smem + OFF_WH + o) = *(const uint4*)(hwh + so);
            *(uint4*)(smem + OFF_WL + o) = *(const uint4*)(hwl + so);
        }
        __syncthreads();

#pragma unroll
        for (int ks = 0; ks < 4; ks++) {
            uint32_t ah[2][4], al[2][4], wh[4][2], wl[4][2];
#pragma unroll
            for (int mt = 0; mt < 2; mt++) {
                const uint32_t ro = (a_row + mt * 16) * PITCH_B + ks * 32 + a_cb;
                LDSM4(ah[mt][0], ah[mt][1], ah[mt][2], ah[mt][3], sb + OFF_AH + ro);
                LDSM4(al[mt][0], al[mt][1], al[mt][2], al[mt][3], sb + OFF_AL + ro);
            }
#pragma unroll
            for (int p = 0; p < 2; p++) {
                const uint32_t ro = (w_row + p * 16) * PITCH_B + ks * 32 + w_cb;
                LDSM4(wh[2 * p][0], wh[2 * p][1], wh[2 * p + 1][0],
                      wh[2 * p + 1][1], sb + OFF_WH + ro);
                LDSM4(wl[2 * p][0], wl[2 * p][1], wl[2 * p + 1][0],
                      wl[2 * p + 1][1], sb + OFF_WL + ro);
            }
#pragma unroll
            for (int mt = 0; mt < 2; mt++)
#pragma unroll
                for (int nt = 0; nt < 4; nt++) {
                    mma_bf16(acc[mt][nt], ah[mt], wh[nt][0], wh[nt][1]);
                    mma_bf16(acc[mt][nt], ah[mt], wl[nt][0], wl[nt][1]);
                    mma_bf16(acc[mt][nt], al[mt], wh[nt][0], wh[nt][1]);
                }
        }
    }

    // epilogue: split to hi/lo, scatter to combined
#pragma unroll
    for (int mt = 0; mt < 2; mt++) {
        const int rowl = wm * 32 + mt * 16 + (lane >> 2);
#pragma unroll
        for (int nt = 0; nt < 4; nt++) {
            const int col = wn * 32 + nt * 8 + 2 * (lane & 3);
            if (col >= COMP) continue;
            const float b0 = bias[col], b1 = bias[col + 1];
#pragma unroll
            for (int h = 0; h < 2; h++) {
                const int r = m0 + rowl + h * 8;
                const int b = r >> 1, c = r & 1;
                const float v0 = acc[mt][nt][2 * h] + b0;
                const float v1 = acc[mt][nt][2 * h + 1] + b1;
                uint32_t hp, lp;
                split_pack(v0, v1, hp, lp);
                const size_t o = (size_t)b * IN_PAD + seg * 100 + c * COMP + col;
                *(uint32_t*)(ch + o) = hp;
                *(uint32_t*)(cl + o) = lp;
            }
        }
    }
}

// =====================================================================
// GEMM on pre-split operands: C = A @ W^T + bias.
// EPI: 0 = plain -> hi/lo out, 1 = leaky -> hi/lo out, 2 = leaky -> fp32
// =====================================================================
template <int EPI>
__global__ __launch_bounds__(256) void k_gemm(
    const __nv_bfloat16* __restrict__ Ah, const __nv_bfloat16* __restrict__ Al,
    int lda, const __nv_bfloat16* __restrict__ Wh,
    const __nv_bfloat16* __restrict__ Wl, int ldw,
    const float* __restrict__ bias, __nv_bfloat16* __restrict__ Ch,
    __nv_bfloat16* __restrict__ Cl, float* __restrict__ Cf, int ldc, int N,
    int K) {
    extern __shared__ __align__(16) char smem[];
    const uint32_t sb = su32(smem);
    const int tid = threadIdx.x, lane = tid & 31, wid = tid >> 5;
    const int wm = wid & 3, wn = wid >> 2;
    const int m0 = blockIdx.x * 128, n0 = blockIdx.y * 64;
    const int nv = (N - n0 < 64) ? (N - n0) : 64;

    float acc[2][4][4] = {};
    const uint32_t a_row = (uint32_t)(wm * 32 + (lane & 15));
    const uint32_t a_cb = (uint32_t)((lane >> 4) << 4);
    const uint32_t w_row = (uint32_t)(wn * 32 + ((lane >> 4) << 3) + (lane & 7));
    const uint32_t w_cb = (uint32_t)((lane & 8) * 2);

    const int nch = (K + 63) >> 6;
    for (int ch = 0; ch < nch; ch++) {
        const int k0 = ch << 6;
        if (ch) __syncthreads();
        // A copy (no guards: K-padded buffers)
#pragma unroll
        for (int i = 0; i < 4; i++) {
            const int idx = i * 256 + tid;
            const int row = idx >> 3, p = idx & 7;
            const size_t so = (size_t)(m0 + row) * lda + k0 + p * 8;
            const uint32_t o = row * PITCH_B + p * 16;
            *(uint4*)(smem + OFF_AH + o) = *(const uint4*)(Ah + so);
            *(uint4*)(smem + OFF_AL + o) = *(const uint4*)(Al + so);
        }
        // W copy (row guard only)
#pragma unroll
        for (int i = 0; i < 2; i++) {
            const int idx = i * 256 + tid;
            const int row = idx >> 3, p = idx & 7;
            const bool rv = row < nv;
            const size_t so = (size_t)(n0 + row) * ldw + k0 + p * 8;
            const uint4 zz = make_uint4(0, 0, 0, 0);
            const uint32_t o = row * PITCH_B + p * 16;
            *(uint4*)(smem + OFF_WH + o) = rv ? *(const uint4*)(Wh + so) : zz;
            *(uint4*)(smem + OFF_WL + o) = rv ? *(const uint4*)(Wl + so) : zz;
        }
        __syncthreads();

#pragma unroll
        for (int ks = 0; ks < 4; ks++) {
            uint32_t ah[2][4], al[2][4], wh[4][2], wl[4][2];
#pragma unroll
            for (int mt = 0; mt < 2; mt++) {
                const uint32_t ro = (a_row + mt * 16) * PITCH_B + ks * 32 + a_cb;
                LDSM4(ah[mt][0], ah[mt][1], ah[mt][2], ah[mt][3], sb + OFF_AH + ro);
                LDSM4(al[mt][0], al[mt][1], al[mt][2], al[mt][3], sb + OFF_AL + ro);
            }
#pragma unroll
            for (int p = 0; p < 2; p++) {
                const uint32_t ro = (w_row + p * 16) * PITCH_B + ks * 32 + w_cb;
                LDSM4(wh[2 * p][0], wh[2 * p][1], wh[2 * p + 1][0],
                      wh[2 * p + 1][1], sb + OFF_WH + ro);
                LDSM4(wl[2 * p][0], wl[2 * p][1], wl[2 * p + 1][0],
                      wl[2 * p + 1][1], sb + OFF_WL + ro);
            }
#pragma unroll
            for (int mt = 0; mt < 2; mt++)
#pragma unroll
                for (int nt = 0; nt < 4; nt++) {
                    mma_bf16(acc[mt][nt], ah[mt], wh[nt][0], wh[nt][1]);
                    mma_bf16(acc[mt][nt], ah[mt], wl[nt][0], wl[nt][1]);
                    mma_bf16(acc[mt][nt], al[mt], wh[nt][0], wh[nt][1]);
                }
        }
    }

#pragma unroll
    for (int mt = 0; mt < 2; mt++) {
        const int rowl = wm * 32 + mt * 16 + (lane >> 2);
#pragma unroll
        for (int nt = 0; nt < 4; nt++) {
            const int col = wn * 32 + nt * 8 + 2 * (lane & 3);
            if (col >= nv) continue;
            const int n = n0 + col;
            const float b0 = bias[n], b1 = bias[n + 1];
#pragma unroll
            for (int h = 0; h < 2; h++) {
                float v0 = acc[mt][nt][2 * h] + b0;
                float v1 = acc[mt][nt][2 * h + 1] + b1;
                if (EPI >= 1) {
                    v0 = v0 > 0.f ? v0 : 0.01f * v0;
                    v1 = v1 > 0.f ? v1 : 0.01f * v1;
                }
                const size_t o = (size_t)(m0 + rowl + h * 8) * ldc + n;
                if (EPI == 2) {
                    *(float2*)(Cf + o) = make_float2(v0, v1);
                } else {
                    uint32_t hp, lp;
                    split_pack(v0, v1, hp, lp);
                    *(uint32_t*)(Ch + o) = hp;
                    *(uint32_t*)(Cl + o) = lp;
                }
            }
        }
    }
}

// final 50 -> 13 layer, fp32
__global__ __launch_bounds__(256) void k_out(
    const float* __restrict__ h2, const float* __restrict__ w3,
    const float* __restrict__ b3, float* __restrict__ out) {
    const int gid = blockIdx.x * 256 + threadIdx.x;
    const int m = gid >> 4, j = gid & 15;
    if (m < BATCH && j < OUT_DIM) {
        float acc = b3[j];
        const float* hr = h2 + (size_t)m * H2_DIM;
        const float* wr = w3 + j * H2_DIM;
#pragma unroll
        for (int k = 0; k < H2_DIM; k++) acc += hr[k] * wr[k];
        out[(size_t)m * OUT_DIM + j] = acc;
    }
}

// =====================================================================
extern "C" void kernel_launch(void* const* d_in, const int* in_sizes, int n_in,
                              void* d_out, int out_size) {
    const float* x      = (const float*)d_in[0];
    const float* head_w = (const float*)d_in[1];
    const float* head_b = (const float*)d_in[2];
    const float* conc_w = (const float*)d_in[3];
    const float* conc_b = (const float*)d_in[4];
    const float* w1     = (const float*)d_in[5];
    const float* b1     = (const float*)d_in[6];
    const float* w2     = (const float*)d_in[7];
    const float* b2     = (const float*)d_in[8];
    const float* w3     = (const float*)d_in[9];
    const float* b3     = (const float*)d_in[10];
    float* out = (float*)d_out;

    __nv_bfloat16 *hwh, *hwl, *cwh, *cwl, *w1h, *w1l, *w2h, *w2l;
    __nv_bfloat16 *chh, *chl, *zh, *zl, *h1h, *h1l;
    float* h2;
    cudaGetSymbolAddress((void**)&hwh, g_hwh);
    cudaGetSymbolAddress((void**)&hwl, g_hwl);
    cudaGetSymbolAddress((void**)&cwh, g_cwh);
    cudaGetSymbolAddress((void**)&cwl, g_cwl);
    cudaGetSymbolAddress((void**)&w1h, g_w1h);
    cudaGetSymbolAddress((void**)&w1l, g_w1l);
    cudaGetSymbolAddress((void**)&w2h, g_w2h);
    cudaGetSymbolAddress((void**)&w2l, g_w2l);
    cudaGetSymbolAddress((void**)&chh, g_ch);
    cudaGetSymbolAddress((void**)&chl, g_cl);
    cudaGetSymbolAddress((void**)&zh, g_zh);
    cudaGetSymbolAddress((void**)&zl, g_zl);
    cudaGetSymbolAddress((void**)&h1h, g_h1h);
    cudaGetSymbolAddress((void**)&h1l, g_h1l);
    cudaGetSymbolAddress((void**)&h2, g_h2);

    cudaFuncSetAttribute(k_heads, cudaFuncAttributeMaxDynamicSharedMemorySize,
                         SMEM_TOTAL);
    cudaFuncSetAttribute(k_gemm<0>, cudaFuncAttributeMaxDynamicSharedMemorySize,
                         SMEM_TOTAL);
    cudaFuncSetAttribute(k_gemm<1>, cudaFuncAttributeMaxDynamicSharedMemorySize,
                         SMEM_TOTAL);
    cudaFuncSetAttribute(k_gemm<2>, cudaFuncAttributeMaxDynamicSharedMemorySize,
                         SMEM_TOTAL);

    // weight pre-split (cheap, every call)
    k_cvt_pad<<<(INPUT_DIM * (INPUT_DIM / 4) + 255) / 256, 256>>>(
        conc_w, cwh, cwl, INPUT_DIM, INPUT_DIM, IN_PAD);
    k_cvt_pad<<<(H1_DIM * (INPUT_DIM / 4) + 255) / 256, 256>>>(
        w1, w1h, w1l, H1_DIM, INPUT_DIM, IN_PAD);
    k_cvt_pad<<<(H2_DIM * (H1_DIM / 4) + 255) / 256, 256>>>(
        w2, w2h, w2l, H2_DIM, H1_DIM, H1_PAD);
    k_cvt_hw<<<dim3((TOTAL_BINS + 255) / 256, COMP), 256>>>(head_w, hwh, hwl);

    // Stage 1: heads -> combined (hi/lo)
    k_heads<<<dim3(ROWS / 128, N_HEADS), 256, SMEM_TOTAL>>>(x, hwh, hwl,
                                                            head_b, chh, chl);
    // Stage 2: z = combined @ conc_w^T + conc_b
    k_gemm<0><<<dim3(BATCH / 128, (INPUT_DIM + 63) / 64), 256, SMEM_TOTAL>>>(
        chh, chl, IN_PAD, cwh, cwl, IN_PAD, conc_b, zh, zl, nullptr, IN_PAD,
        INPUT_DIM, INPUT_DIM);
    // Stage 3: h1 = leaky(z @ w1^T + b1)
    k_gemm<1><<<dim3(BATCH / 128, (H1_DIM + 63) / 64), 256, SMEM_TOTAL>>>(
        zh, zl, IN_PAD, w1h, w1l, IN_PAD, b1, h1h, h1l, nullptr, H1_PAD,
        H1_DIM, INPUT_DIM);
    // Stage 4: h2 = leaky(h1 @ w2^T + b2)  (fp32 out)
    k_gemm<2><<<dim3(BATCH / 128, 1), 256, SMEM_TOTAL>>>(
        h1h, h1l, H1_PAD, w2h, w2l, H1_PAD, b2, nullptr, nullptr, h2, H2_DIM,
        H2_DIM, H1_DIM);
    // Stage 5: out = h2 @ w3^T + b3
    k_out<<<(BATCH * 16 + 255) / 256, 256>>>(h2, w3, b3, out);
}

// round 12
// speedup vs baseline: 1.2732x; 1.0715x over previous
#include <cuda_runtime.h>
#include <cuda_bf16.h>
#include <cstdint>

// ---------------- problem constants ----------------
#define TOTAL_BINS 28749
#define BATCH      2048
#define ROWS       4096
#define INPUT_DIM  2200
#define IN_PAD     2240      // INPUT_DIM padded to 64
#define H1_DIM     1000
#define H1_PAD     1024
#define H2_DIM     50
#define OUT_DIM    13
#define N_HEADS    22
#define COMP       50
#define HW_PAD     29312     // sum of per-segment 64-padded K

__device__ __constant__ int d_LOC[23] = {
    0, 2490, 4912, 6895, 8797, 10612, 12320, 13913, 15364, 16748, 18086,
    19437, 20770, 21914, 22984, 24004, 24907, 25740, 26544, 27130, 27774,
    28241, 28749};
__device__ __constant__ int d_LOC64[23] = {
    0, 2496, 4928, 6912, 8832, 10688, 12416, 14016, 15488, 16896, 18240,
    19648, 20992, 22144, 23232, 24256, 25216, 26112, 26944, 27584, 28288,
    28800, 29312};

// ------- scratch (zero-initialized; pad rows/cols never written) -----
__device__ __nv_bfloat16 g_hwh[64 * HW_PAD];
__device__ __nv_bfloat16 g_hwl[64 * HW_PAD];
__device__ __nv_bfloat16 g_cwh[IN_PAD * IN_PAD];    // N-padded too
__device__ __nv_bfloat16 g_cwl[IN_PAD * IN_PAD];
__device__ __nv_bfloat16 g_w1h[H1_PAD * IN_PAD];
__device__ __nv_bfloat16 g_w1l[H1_PAD * IN_PAD];
__device__ __nv_bfloat16 g_w2h[64 * H1_PAD];
__device__ __nv_bfloat16 g_w2l[64 * H1_PAD];
__device__ __nv_bfloat16 g_ch[BATCH * IN_PAD];
__device__ __nv_bfloat16 g_cl[BATCH * IN_PAD];
__device__ __nv_bfloat16 g_zh[BATCH * IN_PAD];
__device__ __nv_bfloat16 g_zl[BATCH * IN_PAD];
__device__ __nv_bfloat16 g_h1h[BATCH * H1_PAD];
__device__ __nv_bfloat16 g_h1l[BATCH * H1_PAD];
__device__ float         g_h2[BATCH * H2_DIM];

// ---------------- smem tile geometry, pitch 72 bf16 = 144 B ----------
#define PITCH_B   144
#define OFF_AH    0
#define OFF_AL    18432
#define OFF_WH    36864
#define OFF_WL    46080
#define ST_STRIDE 55296                  // one gemm pipeline stage
#define GEMM_SMEM (2 * ST_STRIDE)        // 110592

// heads smem: fp32 staging (2 stages) + W bf16 (2 stages) + A bf16 (1)
#define HX_ST     32768                  // 128 rows x 256 B fp32
#define H_OFFX    0                      // stages at 0, 32768
#define H_OFFW    65536                  // stage stride 18432 (WH+WL)
#define H_WST     18432
#define H_OFFAH   102400
#define H_OFFAL   120832
#define HEADS_SMEM 139264

__device__ __forceinline__ uint32_t su32(const void* p) {
    uint32_t a;
    asm("{ .reg .u64 t; cvta.to.shared.u64 t, %1; cvt.u32.u64 %0, t; }"
        : "=r"(a) : "l"(p));
    return a;
}

#define CP16(dst, src)                                                        \
    asm volatile("cp.async.cg.shared.global [%0], [%1], 16;" ::"r"(dst),      \
                 "l"(src))
#define CP4Z(dst, src, ssz)                                                   \
    asm volatile("cp.async.ca.shared.global [%0], [%1], 4, %2;" ::"r"(dst),   \
                 "l"(src), "r"(ssz))
#define CP_COMMIT asm volatile("cp.async.commit_group;" ::: "memory")
#define CP_WAIT1  asm volatile("cp.async.wait_group 1;" ::: "memory")

#define LDSM4(r0, r1, r2, r3, addr)                                          \
    asm volatile(                                                            \
        "ldmatrix.sync.aligned.m8n8.x4.shared.b16 {%0,%1,%2,%3}, [%4];"      \
        : "=r"(r0), "=r"(r1), "=r"(r2), "=r"(r3) : "r"(addr))

__device__ __forceinline__ void mma_bf16(float* d, const uint32_t* a,
                                         uint32_t b0, uint32_t b1) {
    asm volatile(
        "mma.sync.aligned.m16n8k16.row.col.f32.bf16.bf16.f32 "
        "{%0,%1,%2,%3}, {%4,%5,%6,%7}, {%8,%9}, {%0,%1,%2,%3};"
        : "+f"(d[0]), "+f"(d[1]), "+f"(d[2]), "+f"(d[3])
        : "r"(a[0]), "r"(a[1]), "r"(a[2]), "r"(a[3]), "r"(b0), "r"(b1));
}

__device__ __forceinline__ void split_pack(float v0, float v1, uint32_t& hp,
                                           uint32_t& lp) {
    const __nv_bfloat16 h0 = __float2bfloat16(v0);
    const __nv_bfloat16 h1 = __float2bfloat16(v1);
    const __nv_bfloat16 l0 = __float2bfloat16(v0 - __bfloat162float(h0));
    const __nv_bfloat16 l1 = __float2bfloat16(v1 - __bfloat162float(h1));
    hp = ((uint32_t)__bfloat16_as_ushort(h1) << 16) | __bfloat16_as_ushort(h0);
    lp = ((uint32_t)__bfloat16_as_ushort(l1) << 16) | __bfloat16_as_ushort(l0);
}

// =====================================================================
// Weight pre-split: fp32 [N][K] -> bf16 hi/lo [N][KP] (pads stay zero)
// =====================================================================
__global__ __launch_bounds__(256) void k_cvt_pad(
    const float* __restrict__ src, __nv_bfloat16* __restrict__ dh,
    __nv_bfloat16* __restrict__ dl, int N, int K, int KP) {
    const int k4 = K >> 2;
    const int i4 = blockIdx.x * 256 + threadIdx.x;
    if (i4 >= N * k4) return;
    const int row = i4 / k4, col = (i4 - row * k4) * 4;
    const float4 v = *(const float4*)(src + (size_t)row * K + col);
    uint32_t h0, l0, h1, l1;
    split_pack(v.x, v.y, h0, l0);
    split_pack(v.z, v.w, h1, l1);
    const size_t o = (size_t)row * KP + col;
    *(uint2*)(dh + o) = make_uint2(h0, h1);
    *(uint2*)(dl + o) = make_uint2(l0, l1);
}

// head_w fp32 [50][28749] -> padded [64][HW_PAD] hi/lo (per-seg 64-aligned)
__global__ __launch_bounds__(256) void k_cvt_hw(
    const float* __restrict__ hw, __nv_bfloat16* __restrict__ dh,
    __nv_bfloat16* __restrict__ dl) {
    const int o = blockIdx.y;
    const int kp = blockIdx.x * 256 + threadIdx.x;
    if (kp >= TOTAL_BINS) return;
    int seg = 0;
#pragma unroll
    for (int s = 1; s < 22; s++) seg += (kp >= d_LOC[s]);
    const float v = hw[(size_t)o * TOTAL_BINS + kp];
    const __nv_bfloat16 h = __float2bfloat16(v);
    const size_t off = (size_t)o * HW_PAD + d_LOC64[seg] + (kp - d_LOC[seg]);
    dh[off] = h;
    dl[off] = __float2bfloat16(v - __bfloat162float(h));
}

// =====================================================================
// Heads: cp.async pipelined. x fp32 -> smem staging (zero-filled pads)
// -> convert to bf16 hi/lo -> mma with padded W hi/lo (3 products).
// Tile 128 x 64(=50), K-chunk 64, 256 thr (warps 4m x 2n).
// =====================================================================
__global__ __launch_bounds__(256, 1) void k_heads(
    const float* __restrict__ x, const __nv_bfloat16* __restrict__ hwh,
    const __nv_bfloat16* __restrict__ hwl, const float* __restrict__ hb,
    __nv_bfloat16* __restrict__ ch, __nv_bfloat16* __restrict__ cl) {
    extern __shared__ __align__(16) char smem[];
    const uint32_t sb = su32(smem);
    const int tid = threadIdx.x, lane = tid & 31, wid = tid >> 5;
    const int wm = wid & 3, wn = wid >> 2;
    const int m0 = blockIdx.x * 128, seg = blockIdx.y;
    const int a = d_LOC[seg], Ks = d_LOC[seg + 1] - a;
    const int kb = d_LOC64[seg];
    const int nch = (d_LOC64[seg + 1] - kb) >> 6;
    const float* bias = hb + seg * COMP;

    float acc[2][4][4] = {};
    const uint32_t a_row = (uint32_t)(wm * 32 + (lane & 15));
    const uint32_t a_cb = (uint32_t)((lane >> 4) << 4);
    const uint32_t w_row = (uint32_t)(wn * 32 + ((lane >> 4) << 3) + (lane & 7));
    const uint32_t w_cb = (uint32_t)((lane & 8) * 2);

    // ---- chunk loader: X fp32 (4B cp.async, zero-fill pads), W bf16 ----
    auto load_chunk = [&](int ck, int s) {
        const int k0 = ck << 6;
#pragma unroll
        for (int i = 0; i < 32; i++) {
            const int idx = i * 256 + tid;
            const int row = idx >> 6, f = idx & 63;
            const float* src = x + (size_t)(m0 + row) * TOTAL_BINS + a + k0 + f;
            const uint32_t dst = sb + H_OFFX + s * HX_ST + row * 256 + f * 4;
            const int ssz = (k0 + f < Ks) ? 4 : 0;
            CP4Z(dst, src, ssz);
        }
#pragma unroll
        for (int i = 0; i < 2; i++) {
            const int idx = i * 256 + tid;
            const int row = idx >> 3, p = idx & 7;
            const size_t so = (size_t)row * HW_PAD + kb + k0 + p * 8;
            const uint32_t dst = sb + H_OFFW + s * H_WST + row * PITCH_B + p * 16;
            CP16(dst, hwh + so);
            CP16(dst + 9216, hwl + so);
        }
    };

    load_chunk(0, 0);
    CP_COMMIT;

    for (int ck = 0; ck < nch; ck++) {
        const int s = ck & 1;
        if (ck + 1 < nch) load_chunk(ck + 1, (ck + 1) & 1);
        CP_COMMIT;
        CP_WAIT1;
        __syncthreads();

        // convert staging fp32 -> bf16 hi/lo tiles (pads already zero)
#pragma unroll
        for (int i = 0; i < 16; i++) {
            const int idx = i * 256 + tid;
            const int row = idx >> 5, kp = idx & 31;
            const float2 v =
                *(const float2*)(smem + H_OFFX + s * HX_ST + row * 256 + kp * 8);
            uint32_t hp, lp;
            split_pack(v.x, v.y, hp, lp);
            const uint32_t o = row * PITCH_B + kp * 4;
            *(uint32_t*)(smem + H_OFFAH + o) = hp;
            *(uint32_t*)(smem + H_OFFAL + o) = lp;
        }
        __syncthreads();

        const uint32_t wbase = sb + H_OFFW + s * H_WST;
#pragma unroll
        for (int ks = 0; ks < 4; ks++) {
            uint32_t ah[2][4], al[2][4], wh[4][2], wl[4][2];
#pragma unroll
            for (int mt = 0; mt < 2; mt++) {
                const uint32_t ro = (a_row + mt * 16) * PITCH_B + ks * 32 + a_cb;
                LDSM4(ah[mt][0], ah[mt][1], ah[mt][2], ah[mt][3],
                      sb + H_OFFAH + ro);
                LDSM4(al[mt][0], al[mt][1], al[mt][2], al[mt][3],
                      sb + H_OFFAL + ro);
            }
#pragma unroll
            for (int p = 0; p < 2; p++) {
                const uint32_t ro = (w_row + p * 16) * PITCH_B + ks * 32 + w_cb;
                LDSM4(wh[2 * p][0], wh[2 * p][1], wh[2 * p + 1][0],
                      wh[2 * p + 1][1], wbase + ro);
                LDSM4(wl[2 * p][0], wl[2 * p][1], wl[2 * p + 1][0],
                      wl[2 * p + 1][1], wbase + 9216 + ro);
            }
#pragma unroll
            for (int mt = 0; mt < 2; mt++)
#pragma unroll
                for (int nt = 0; nt < 4; nt++) {
                    mma_bf16(acc[mt][nt], ah[mt], wh[nt][0], wh[nt][1]);
                    mma_bf16(acc[mt][nt], ah[mt], wl[nt][0], wl[nt][1]);
                    mma_bf16(acc[mt][nt], al[mt], wh[nt][0], wh[nt][1]);
                }
        }
        __syncthreads();
    }

    // epilogue: split to hi/lo, scatter to combined
#pragma unroll
    for (int mt = 0; mt < 2; mt++) {
        const int rowl = wm * 32 + mt * 16 + (lane >> 2);
#pragma unroll
        for (int nt = 0; nt < 4; nt++) {
            const int col = wn * 32 + nt * 8 + 2 * (lane & 3);
            if (col >= COMP) continue;
            const float b0 = bias[col], b1 = bias[col + 1];
#pragma unroll
            for (int h = 0; h < 2; h++) {
                const int r = m0 + rowl + h * 8;
                const int b = r >> 1, c = r & 1;
                const float v0 = acc[mt][nt][2 * h] + b0;
                const float v1 = acc[mt][nt][2 * h + 1] + b1;
                uint32_t hp, lp;
                split_pack(v0, v1, hp, lp);
                const size_t o = (size_t)b * IN_PAD + seg * 100 + c * COMP + col;
                *(uint32_t*)(ch + o) = hp;
                *(uint32_t*)(cl + o) = lp;
            }
        }
    }
}

// =====================================================================
// GEMM on pre-split N-and-K-padded operands, cp.async double-buffered.
// EPI: 0 = plain -> hi/lo out, 1 = leaky -> hi/lo out, 2 = leaky -> fp32
// =====================================================================
template <int EPI>
__global__ __launch_bounds__(256, 2) void k_gemm(
    const __nv_bfloat16* __restrict__ Ah, const __nv_bfloat16* __restrict__ Al,
    int lda, const __nv_bfloat16* __restrict__ Wh,
    const __nv_bfloat16* __restrict__ Wl, int ldw,
    const float* __restrict__ bias, __nv_bfloat16* __restrict__ Ch,
    __nv_bfloat16* __restrict__ Cl, float* __restrict__ Cf, int ldc, int N,
    int K) {
    extern __shared__ __align__(16) char smem[];
    const uint32_t sb = su32(smem);
    const int tid = threadIdx.x, lane = tid & 31, wid = tid >> 5;
    const int wm = wid & 3, wn = wid >> 2;
    const int m0 = blockIdx.x * 128, n0 = blockIdx.y * 64;
    const int nv = (N - n0 < 64) ? (N - n0) : 64;

    float acc[2][4][4] = {};
    const uint32_t a_row = (uint32_t)(wm * 32 + (lane & 15));
    const uint32_t a_cb = (uint32_t)((lane >> 4) << 4);
    const uint32_t w_row = (uint32_t)(wn * 32 + ((lane >> 4) << 3) + (lane & 7));
    const uint32_t w_cb = (uint32_t)((lane & 8) * 2);

    // guard-free loader: operands padded in both N and K
    auto load_chunk = [&](int ck, int s) {
        const int k0 = ck << 6;
        const uint32_t sbase = sb + s * ST_STRIDE;
#pragma unroll
        for (int i = 0; i < 4; i++) {
            const int idx = i * 256 + tid;
            const int row = idx >> 3, p = idx & 7;
            const size_t so = (size_t)(m0 + row) * lda + k0 + p * 8;
            const uint32_t o = sbase + row * PITCH_B + p * 16;
            CP16(o + OFF_AH, Ah + so);
            CP16(o + OFF_AL, Al + so);
        }
#pragma unroll
        for (int i = 0; i < 2; i++) {
            const int idx = i * 256 + tid;
            const int row = idx >> 3, p = idx & 7;
            const size_t so = (size_t)(n0 + row) * ldw + k0 + p * 8;
            const uint32_t o = sbase + row * PITCH_B + p * 16;
            CP16(o + OFF_WH, Wh + so);
            CP16(o + OFF_WL, Wl + so);
        }
    };

    const int nch = (K + 63) >> 6;
    load_chunk(0, 0);
    CP_COMMIT;

    for (int ck = 0; ck < nch; ck++) {
        if (ck + 1 < nch) load_chunk(ck + 1, (ck + 1) & 1);
        CP_COMMIT;
        CP_WAIT1;
        __syncthreads();

        const uint32_t sbase = sb + (ck & 1) * ST_STRIDE;
#pragma unroll
        for (int ks = 0; ks < 4; ks++) {
            uint32_t ah[2][4], al[2][4], wh[4][2], wl[4][2];
#pragma unroll
            for (int mt = 0; mt < 2; mt++) {
                const uint32_t ro = (a_row + mt * 16) * PITCH_B + ks * 32 + a_cb;
                LDSM4(ah[mt][0], ah[mt][1], ah[mt][2], ah[mt][3],
                      sbase + OFF_AH + ro);
                LDSM4(al[mt][0], al[mt][1], al[mt][2], al[mt][3],
                      sbase + OFF_AL + ro);
            }
#pragma unroll
            for (int p = 0; p < 2; p++) {
                const uint32_t ro = (w_row + p * 16) * PITCH_B + ks * 32 + w_cb;
                LDSM4(wh[2 * p][0], wh[2 * p][1], wh[2 * p + 1][0],
                      wh[2 * p + 1][1], sbase + OFF_WH + ro);
                LDSM4(wl[2 * p][0], wl[2 * p][1], wl[2 * p + 1][0],
                      wl[2 * p + 1][1], sbase + OFF_WL + ro);
            }
#pragma unroll
            for (int mt = 0; mt < 2; mt++)
#pragma unroll
                for (int nt = 0; nt < 4; nt++) {
                    mma_bf16(acc[mt][nt], ah[mt], wh[nt][0], wh[nt][1]);
                    mma_bf16(acc[mt][nt], ah[mt], wl[nt][0], wl[nt][1]);
                    mma_bf16(acc[mt][nt], al[mt], wh[nt][0], wh[nt][1]);
                }
        }
        __syncthreads();
    }

#pragma unroll
    for (int mt = 0; mt < 2; mt++) {
        const int rowl = wm * 32 + mt * 16 + (lane >> 2);
#pragma unroll
        for (int nt = 0; nt < 4; nt++) {
            const int col = wn * 32 + nt * 8 + 2 * (lane & 3);
            if (col >= nv) continue;
            const int n = n0 + col;
            const float b0 = bias[n], b1 = bias[n + 1];
#pragma unroll
            for (int h = 0; h < 2; h++) {
                float v0 = acc[mt][nt][2 * h] + b0;
                float v1 = acc[mt][nt][2 * h + 1] + b1;
                if (EPI >= 1) {
                    v0 = v0 > 0.f ? v0 : 0.01f * v0;
                    v1 = v1 > 0.f ? v1 : 0.01f * v1;
                }
                const size_t o = (size_t)(m0 + rowl + h * 8) * ldc + n;
                if (EPI == 2) {
                    *(float2*)(Cf + o) = make_float2(v0, v1);
                } else {
                    uint32_t hp, lp;
                    split_pack(v0, v1, hp, lp);
                    *(uint32_t*)(Ch + o) = hp;
                    *(uint32_t*)(Cl + o) = lp;
                }
            }
        }
    }
}

// final 50 -> 13 layer, fp32
__global__ __launch_bounds__(256) void k_out(
    const float* __restrict__ h2, const float* __restrict__ w3,
    const float* __restrict__ b3, float* __restrict__ out) {
    const int gid = blockIdx.x * 256 + threadIdx.x;
    const int m = gid >> 4, j = gid & 15;
    if (m < BATCH && j < OUT_DIM) {
        float acc = b3[j];
        const float* hr = h2 + (size_t)m * H2_DIM;
        const float* wr = w3 + j * H2_DIM;
#pragma unroll
        for (int k = 0; k < H2_DIM; k++) acc += hr[k] * wr[k];
        out[(size_t)m * OUT_DIM + j] = acc;
    }
}

// =====================================================================
extern "C" void kernel_launch(void* const* d_in, const int* in_sizes, int n_in,
                              void* d_out, int out_size) {
    const float* x      = (const float*)d_in[0];
    const float* head_w = (const float*)d_in[1];
    const float* head_b = (const float*)d_in[2];
    const float* conc_w = (const float*)d_in[3];
    const float* conc_b = (const float*)d_in[4];
    const float* w1     = (const float*)d_in[5];
    const float* b1     = (const float*)d_in[6];
    const float* w2     = (const float*)d_in[7];
    const float* b2     = (const float*)d_in[8];
    const float* w3     = (const float*)d_in[9];
    const float* b3     = (const float*)d_in[10];
    float* out = (float*)d_out;

    __nv_bfloat16 *hwh, *hwl, *cwh, *cwl, *w1h, *w1l, *w2h, *w2l;
    __nv_bfloat16 *chh, *chl, *zh, *zl, *h1h, *h1l;
    float* h2;
    cudaGetSymbolAddress((void**)&hwh, g_hwh);
    cudaGetSymbolAddress((void**)&hwl, g_hwl);
    cudaGetSymbolAddress((void**)&cwh, g_cwh);
    cudaGetSymbolAddress((void**)&cwl, g_cwl);
    cudaGetSymbolAddress((void**)&w1h, g_w1h);
    cudaGetSymbolAddress((void**)&w1l, g_w1l);
    cudaGetSymbolAddress((void**)&w2h, g_w2h);
    cudaGetSymbolAddress((void**)&w2l, g_w2l);
    cudaGetSymbolAddress((void**)&chh, g_ch);
    cudaGetSymbolAddress((void**)&chl, g_cl);
    cudaGetSymbolAddress((void**)&zh, g_zh);
    cudaGetSymbolAddress((void**)&zl, g_zl);
    cudaGetSymbolAddress((void**)&h1h, g_h1h);
    cudaGetSymbolAddress((void**)&h1l, g_h1l);
    cudaGetSymbolAddress((void**)&h2, g_h2);

    cudaFuncSetAttribute(k_heads, cudaFuncAttributeMaxDynamicSharedMemorySize,
                         HEADS_SMEM);
    cudaFuncSetAttribute(k_gemm<0>, cudaFuncAttributeMaxDynamicSharedMemorySize,
                         GEMM_SMEM);
    cudaFuncSetAttribute(k_gemm<1>, cudaFuncAttributeMaxDynamicSharedMemorySize,
                         GEMM_SMEM);
    cudaFuncSetAttribute(k_gemm<2>, cudaFuncAttributeMaxDynamicSharedMemorySize,
                         GEMM_SMEM);

    // weight pre-split (cheap, every call)
    k_cvt_pad<<<(INPUT_DIM * (INPUT_DIM / 4) + 255) / 256, 256>>>(
        conc_w, cwh, cwl, INPUT_DIM, INPUT_DIM, IN_PAD);
    k_cvt_pad<<<(H1_DIM * (INPUT_DIM / 4) + 255) / 256, 256>>>(
        w1, w1h, w1l, H1_DIM, INPUT_DIM, IN_PAD);
    k_cvt_pad<<<(H2_DIM * (H1_DIM / 4) + 255) / 256, 256>>>(
        w2, w2h, w2l, H2_DIM, H1_DIM, H1_PAD);
    k_cvt_hw<<<dim3((TOTAL_BINS + 255) / 256, COMP), 256>>>(head_w, hwh, hwl);

    // Stage 1: heads -> combined (hi/lo)
    k_heads<<<dim3(ROWS / 128, N_HEADS), 256, HEADS_SMEM>>>(x, hwh, hwl,
                                                            head_b, chh, chl);
    // Stage 2: z = combined @ conc_w^T + conc_b
    k_gemm<0><<<dim3(BATCH / 128, (INPUT_DIM + 63) / 64), 256, GEMM_SMEM>>>(
        chh, chl, IN_PAD, cwh, cwl, IN_PAD, conc_b, zh, zl, nullptr, IN_PAD,
        INPUT_DIM, INPUT_DIM);
    // Stage 3: h1 = leaky(z @ w1^T + b1)
    k_gemm<1><<<dim3(BATCH / 128, (H1_DIM + 63) / 64), 256, GEMM_SMEM>>>(
        zh, zl, IN_PAD, w1h, w1l, IN_PAD, b1, h1h, h1l, nullptr, H1_PAD,
        H1_DIM, INPUT_DIM);
    // Stage 4: h2 = leaky(h1 @ w2^T + b2)  (fp32 out)
    k_gemm<2><<<dim3(BATCH / 128, 1), 256, GEMM_SMEM>>>(
        h1h, h1l, H1_PAD, w2h, w2l, H1_PAD, b2, nullptr, nullptr, h2, H2_DIM,
        H2_DIM, H1_DIM);
    // Stage 5: out = h2 @ w3^T + b3
    k_out<<<(BATCH * 16 + 255) / 256, 256>>>(h2, w3, b3, out);
}

// round 13
// speedup vs baseline: 1.7824x; 1.4000x over previous
#include <cuda_runtime.h>
#include <cuda_fp16.h>
#include <cstdint>

// ---------------- problem constants ----------------
#define TOTAL_BINS 28749
#define BATCH      2048
#define ROWS       4096
#define INPUT_DIM  2200
#define IN_PAD     2240      // INPUT_DIM padded to 64
#define H1_DIM     1000
#define H1_PAD     1024
#define H2_DIM     50
#define OUT_DIM    13
#define N_HEADS    22
#define COMP       50
#define HW_PAD     29312     // sum of per-segment 64-padded K

__device__ __constant__ int d_LOC[23] = {
    0, 2490, 4912, 6895, 8797, 10612, 12320, 13913, 15364, 16748, 18086,
    19437, 20770, 21914, 22984, 24004, 24907, 25740, 26544, 27130, 27774,
    28241, 28749};
__device__ __constant__ int d_LOC64[23] = {
    0, 2496, 4928, 6912, 8832, 10688, 12416, 14016, 15488, 16896, 18240,
    19648, 20992, 22144, 23232, 24256, 25216, 26112, 26944, 27584, 28288,
    28800, 29312};

// ------- scratch (zero-initialized; pad rows/cols never written) -----
__device__ __half g_hwh[64 * HW_PAD];          // head_w f16 hi
__device__ __half g_hwl[64 * HW_PAD];          // head_w f16 lo
__device__ __half g_cwh[IN_PAD * IN_PAD];
__device__ __half g_cwl[IN_PAD * IN_PAD];
__device__ __half g_w1h[H1_PAD * IN_PAD];
__device__ __half g_w1l[H1_PAD * IN_PAD];
__device__ __half g_w2h[64 * H1_PAD];
__device__ __half g_w2l[64 * H1_PAD];
__device__ __half g_ch[BATCH * IN_PAD];        // activations: hi only
__device__ __half g_zh[BATCH * IN_PAD];
__device__ __half g_h1h[BATCH * H1_PAD];
__device__ float  g_h2[BATCH * H2_DIM];

// ---------------- smem tile geometry, pitch 72 f16 = 144 B -----------
#define PITCH_B   144
// gemm stage: A hi (128x144=18432) + W hi (9216) + W lo (9216)
#define OFF_AH    0
#define OFF_WH    18432
#define OFF_WL    27648
#define ST_STRIDE 36864
#define GEMM_SMEM (2 * ST_STRIDE)        // 73728

// heads: fp32 x staging (2 x 32768) + W hi/lo (2 x 18432) + A hi (18432)
#define HX_ST     32768
#define H_OFFX    0
#define H_OFFW    65536
#define H_WST     18432
#define H_OFFAH   102400
#define HEADS_SMEM 120832

__device__ __forceinline__ uint32_t su32(const void* p) {
    uint32_t a;
    asm("{ .reg .u64 t; cvta.to.shared.u64 t, %1; cvt.u32.u64 %0, t; }"
        : "=r"(a) : "l"(p));
    return a;
}

#define CP16(dst, src)                                                        \
    asm volatile("cp.async.cg.shared.global [%0], [%1], 16;" ::"r"(dst),      \
                 "l"(src))
#define CP4Z(dst, src, ssz)                                                   \
    asm volatile("cp.async.ca.shared.global [%0], [%1], 4, %2;" ::"r"(dst),   \
                 "l"(src), "r"(ssz))
#define CP_COMMIT asm volatile("cp.async.commit_group;" ::: "memory")
#define CP_WAIT1  asm volatile("cp.async.wait_group 1;" ::: "memory")

#define LDSM4(r0, r1, r2, r3, addr)                                          \
    asm volatile(                                                            \
        "ldmatrix.sync.aligned.m8n8.x4.shared.b16 {%0,%1,%2,%3}, [%4];"      \
        : "=r"(r0), "=r"(r1), "=r"(r2), "=r"(r3) : "r"(addr))

__device__ __forceinline__ void mma_f16(float* d, const uint32_t* a,
                                        uint32_t b0, uint32_t b1) {
    asm volatile(
        "mma.sync.aligned.m16n8k16.row.col.f32.f16.f16.f32 "
        "{%0,%1,%2,%3}, {%4,%5,%6,%7}, {%8,%9}, {%0,%1,%2,%3};"
        : "+f"(d[0]), "+f"(d[1]), "+f"(d[2]), "+f"(d[3])
        : "r"(a[0]), "r"(a[1]), "r"(a[2]), "r"(a[3]), "r"(b0), "r"(b1));
}

// f16 hi/lo split of a pair
__device__ __forceinline__ void split_pack(float v0, float v1, uint32_t& hp,
                                           uint32_t& lp) {
    __half2 h = __floats2half2_rn(v0, v1);
    float2 hf = __half22float2(h);
    __half2 l = __floats2half2_rn(v0 - hf.x, v1 - hf.y);
    hp = *(uint32_t*)&h;
    lp = *(uint32_t*)&l;
}
// hi-only pack
__device__ __forceinline__ uint32_t pack_hi(float v0, float v1) {
    __half2 h = __floats2half2_rn(v0, v1);
    return *(uint32_t*)&h;
}

// =====================================================================
// Weight pre-split: fp32 [N][K] -> f16 hi/lo [N][KP] (pads stay zero)
// =====================================================================
__global__ __launch_bounds__(256) void k_cvt_pad(
    const float* __restrict__ src, __half* __restrict__ dh,
    __half* __restrict__ dl, int N, int K, int KP) {
    const int k4 = K >> 2;
    const int i4 = blockIdx.x * 256 + threadIdx.x;
    if (i4 >= N * k4) return;
    const int row = i4 / k4, col = (i4 - row * k4) * 4;
    const float4 v = *(const float4*)(src + (size_t)row * K + col);
    uint32_t h0, l0, h1, l1;
    split_pack(v.x, v.y, h0, l0);
    split_pack(v.z, v.w, h1, l1);
    const size_t o = (size_t)row * KP + col;
    *(uint2*)(dh + o) = make_uint2(h0, h1);
    *(uint2*)(dl + o) = make_uint2(l0, l1);
}

// head_w fp32 [50][28749] -> padded [64][HW_PAD] hi/lo (per-seg 64-aligned)
__global__ __launch_bounds__(256) void k_cvt_hw(
    const float* __restrict__ hw, __half* __restrict__ dh,
    __half* __restrict__ dl) {
    const int o = blockIdx.y;
    const int kp = blockIdx.x * 256 + threadIdx.x;
    if (kp >= TOTAL_BINS) return;
    int seg = 0;
#pragma unroll
    for (int s = 1; s < 22; s++) seg += (kp >= d_LOC[s]);
    const float v = hw[(size_t)o * TOTAL_BINS + kp];
    const __half h = __float2half_rn(v);
    const size_t off = (size_t)o * HW_PAD + d_LOC64[seg] + (kp - d_LOC[seg]);
    dh[off] = h;
    dl[off] = __float2half_rn(v - __half2float(h));
}

// =====================================================================
// Heads: cp.async pipelined. x fp32 -> smem staging (zero-filled pads)
// -> convert to f16 hi -> 2-product mma with padded W hi/lo.
// Tile 128 x 64(=50), K-chunk 64, 256 thr (warps 4m x 2n).
// =====================================================================
__global__ __launch_bounds__(256, 1) void k_heads(
    const float* __restrict__ x, const __half* __restrict__ hwh,
    const __half* __restrict__ hwl, const float* __restrict__ hb,
    __half* __restrict__ ch) {
    extern __shared__ __align__(16) char smem[];
    const uint32_t sb = su32(smem);
    const int tid = threadIdx.x, lane = tid & 31, wid = tid >> 5;
    const int wm = wid & 3, wn = wid >> 2;
    const int m0 = blockIdx.x * 128, seg = blockIdx.y;
    const int a = d_LOC[seg], Ks = d_LOC[seg + 1] - a;
    const int kb = d_LOC64[seg];
    const int nch = (d_LOC64[seg + 1] - kb) >> 6;
    const float* bias = hb + seg * COMP;

    float acc[2][4][4] = {};
    const uint32_t a_row = (uint32_t)(wm * 32 + (lane & 15));
    const uint32_t a_cb = (uint32_t)((lane >> 4) << 4);
    const uint32_t w_row = (uint32_t)(wn * 32 + ((lane >> 4) << 3) + (lane & 7));
    const uint32_t w_cb = (uint32_t)((lane & 8) * 2);

    auto load_chunk = [&](int ck, int s) {
        const int k0 = ck << 6;
#pragma unroll
        for (int i = 0; i < 32; i++) {
            const int idx = i * 256 + tid;
            const int row = idx >> 6, f = idx & 63;
            const float* src = x + (size_t)(m0 + row) * TOTAL_BINS + a + k0 + f;
            const uint32_t dst = sb + H_OFFX + s * HX_ST + row * 256 + f * 4;
            const int ssz = (k0 + f < Ks) ? 4 : 0;
            CP4Z(dst, src, ssz);
        }
#pragma unroll
        for (int i = 0; i < 2; i++) {
            const int idx = i * 256 + tid;
            const int row = idx >> 3, p = idx & 7;
            const size_t so = (size_t)row * HW_PAD + kb + k0 + p * 8;
            const uint32_t dst = sb + H_OFFW + s * H_WST + row * PITCH_B + p * 16;
            CP16(dst, hwh + so);
            CP16(dst + 9216, hwl + so);
        }
    };

    load_chunk(0, 0);
    CP_COMMIT;

    for (int ck = 0; ck < nch; ck++) {
        const int s = ck & 1;
        if (ck + 1 < nch) load_chunk(ck + 1, (ck + 1) & 1);
        CP_COMMIT;
        CP_WAIT1;
        __syncthreads();

        // convert staged fp32 -> f16 hi tile (pads already zero)
#pragma unroll
        for (int i = 0; i < 16; i++) {
            const int idx = i * 256 + tid;
            const int row = idx >> 5, kp = idx & 31;
            const float2 v =
                *(const float2*)(smem + H_OFFX + s * HX_ST + row * 256 + kp * 8);
            *(uint32_t*)(smem + H_OFFAH + row * PITCH_B + kp * 4) =
                pack_hi(v.x, v.y);
        }
        __syncthreads();

        const uint32_t wbase = sb + H_OFFW + s * H_WST;
#pragma unroll
        for (int ks = 0; ks < 4; ks++) {
            uint32_t ah[2][4], wh[4][2], wl[4][2];
#pragma unroll
            for (int mt = 0; mt < 2; mt++) {
                const uint32_t ro = (a_row + mt * 16) * PITCH_B + ks * 32 + a_cb;
                LDSM4(ah[mt][0], ah[mt][1], ah[mt][2], ah[mt][3],
                      sb + H_OFFAH + ro);
            }
#pragma unroll
            for (int p = 0; p < 2; p++) {
                const uint32_t ro = (w_row + p * 16) * PITCH_B + ks * 32 + w_cb;
                LDSM4(wh[2 * p][0], wh[2 * p][1], wh[2 * p + 1][0],
                      wh[2 * p + 1][1], wbase + ro);
                LDSM4(wl[2 * p][0], wl[2 * p][1], wl[2 * p + 1][0],
                      wl[2 * p + 1][1], wbase + 9216 + ro);
            }
#pragma unroll
            for (int mt = 0; mt < 2; mt++)
#pragma unroll
                for (int nt = 0; nt < 4; nt++) {
                    mma_f16(acc[mt][nt], ah[mt], wh[nt][0], wh[nt][1]);
                    mma_f16(acc[mt][nt], ah[mt], wl[nt][0], wl[nt][1]);
                }
        }
        __syncthreads();
    }

    // epilogue: pack hi, scatter to combined
#pragma unroll
    for (int mt = 0; mt < 2; mt++) {
        const int rowl = wm * 32 + mt * 16 + (lane >> 2);
#pragma unroll
        for (int nt = 0; nt < 4; nt++) {
            const int col = wn * 32 + nt * 8 + 2 * (lane & 3);
            if (col >= COMP) continue;
            const float b0 = bias[col], b1 = bias[col + 1];
#pragma unroll
            for (int h = 0; h < 2; h++) {
                const int r = m0 + rowl + h * 8;
                const int b = r >> 1, c = r & 1;
                const size_t o = (size_t)b * IN_PAD + seg * 100 + c * COMP + col;
                *(uint32_t*)(ch + o) =
                    pack_hi(acc[mt][nt][2 * h] + b0, acc[mt][nt][2 * h + 1] + b1);
            }
        }
    }
}

// =====================================================================
// GEMM: A f16 hi, W f16 hi/lo (2 products), cp.async double-buffered.
// EPI: 0 = plain -> hi out, 1 = leaky -> hi out, 2 = leaky -> fp32
// =====================================================================
template <int EPI>
__global__ __launch_bounds__(256, 2) void k_gemm(
    const __half* __restrict__ Ah, int lda, const __half* __restrict__ Wh,
    const __half* __restrict__ Wl, int ldw, const float* __restrict__ bias,
    __half* __restrict__ Ch, float* __restrict__ Cf, int ldc, int N, int K) {
    extern __shared__ __align__(16) char smem[];
    const uint32_t sb = su32(smem);
    const int tid = threadIdx.x, lane = tid & 31, wid = tid >> 5;
    const int wm = wid & 3, wn = wid >> 2;
    const int m0 = blockIdx.x * 128, n0 = blockIdx.y * 64;
    const int nv = (N - n0 < 64) ? (N - n0) : 64;

    float acc[2][4][4] = {};
    const uint32_t a_row = (uint32_t)(wm * 32 + (lane & 15));
    const uint32_t a_cb = (uint32_t)((lane >> 4) << 4);
    const uint32_t w_row = (uint32_t)(wn * 32 + ((lane >> 4) << 3) + (lane & 7));
    const uint32_t w_cb = (uint32_t)((lane & 8) * 2);

    auto load_chunk = [&](int ck, int s) {
        const int k0 = ck << 6;
        const uint32_t sbase = sb + s * ST_STRIDE;
#pragma unroll
        for (int i = 0; i < 4; i++) {
            const int idx = i * 256 + tid;
            const int row = idx >> 3, p = idx & 7;
            const size_t so = (size_t)(m0 + row) * lda + k0 + p * 8;
            CP16(sbase + OFF_AH + row * PITCH_B + p * 16, Ah + so);
        }
#pragma unroll
        for (int i = 0; i < 2; i++) {
            const int idx = i * 256 + tid;
            const int row = idx >> 3, p = idx & 7;
            const size_t so = (size_t)(n0 + row) * ldw + k0 + p * 8;
            const uint32_t o = sbase + row * PITCH_B + p * 16;
            CP16(o + OFF_WH, Wh + so);
            CP16(o + OFF_WL, Wl + so);
        }
    };

    const int nch = (K + 63) >> 6;
    load_chunk(0, 0);
    CP_COMMIT;

    for (int ck = 0; ck < nch; ck++) {
        if (ck + 1 < nch) load_chunk(ck + 1, (ck + 1) & 1);
        CP_COMMIT;
        CP_WAIT1;
        __syncthreads();

        const uint32_t sbase = sb + (ck & 1) * ST_STRIDE;
#pragma unroll
        for (int ks = 0; ks < 4; ks++) {
            uint32_t ah[2][4], wh[4][2], wl[4][2];
#pragma unroll
            for (int mt = 0; mt < 2; mt++) {
                const uint32_t ro = (a_row + mt * 16) * PITCH_B + ks * 32 + a_cb;
                LDSM4(ah[mt][0], ah[mt][1], ah[mt][2], ah[mt][3],
                      sbase + OFF_AH + ro);
            }
#pragma unroll
            for (int p = 0; p < 2; p++) {
                const uint32_t ro = (w_row + p * 16) * PITCH_B + ks * 32 + w_cb;
                LDSM4(wh[2 * p][0], wh[2 * p][1], wh[2 * p + 1][0],
                      wh[2 * p + 1][1], sbase + OFF_WH + ro);
                LDSM4(wl[2 * p][0], wl[2 * p][1], wl[2 * p + 1][0],
                      wl[2 * p + 1][1], sbase + OFF_WL + ro);
            }
#pragma unroll
            for (int mt = 0; mt < 2; mt++)
#pragma unroll
                for (int nt = 0; nt < 4; nt++) {
                    mma_f16(acc[mt][nt], ah[mt], wh[nt][0], wh[nt][1]);
                    mma_f16(acc[mt][nt], ah[mt], wl[nt][0], wl[nt][1]);
                }
        }
        __syncthreads();
    }

#pragma unroll
    for (int mt = 0; mt < 2; mt++) {
        const int rowl = wm * 32 + mt * 16 + (lane >> 2);
#pragma unroll
        for (int nt = 0; nt < 4; nt++) {
            const int col = wn * 32 + nt * 8 + 2 * (lane & 3);
            if (col >= nv) continue;
            const int n = n0 + col;
            const float b0 = bias[n], b1 = bias[n + 1];
#pragma unroll
            for (int h = 0; h < 2; h++) {
                float v0 = acc[mt][nt][2 * h] + b0;
                float v1 = acc[mt][nt][2 * h + 1] + b1;
                if (EPI >= 1) {
                    v0 = v0 > 0.f ? v0 : 0.01f * v0;
                    v1 = v1 > 0.f ? v1 : 0.01f * v1;
                }
                const size_t o = (size_t)(m0 + rowl + h * 8) * ldc + n;
                if (EPI == 2)
                    *(float2*)(Cf + o) = make_float2(v0, v1);
                else
                    *(uint32_t*)(Ch + o) = pack_hi(v0, v1);
            }
        }
    }
}

// final 50 -> 13 layer, fp32
__global__ __launch_bounds__(256) void k_out(
    const float* __restrict__ h2, const float* __restrict__ w3,
    const float* __restrict__ b3, float* __restrict__ out) {
    const int gid = blockIdx.x * 256 + threadIdx.x;
    const int m = gid >> 4, j = gid & 15;
    if (m < BATCH && j < OUT_DIM) {
        float acc = b3[j];
        const float* hr = h2 + (size_t)m * H2_DIM;
        const float* wr = w3 + j * H2_DIM;
#pragma unroll
        for (int k = 0; k < H2_DIM; k++) acc += hr[k] * wr[k];
        out[(size_t)m * OUT_DIM + j] = acc;
    }
}

// =====================================================================
extern "C" void kernel_launch(void* const* d_in, const int* in_sizes, int n_in,
                              void* d_out, int out_size) {
    const float* x      = (const float*)d_in[0];
    const float* head_w = (const float*)d_in[1];
    const float* head_b = (const float*)d_in[2];
    const float* conc_w = (const float*)d_in[3];
    const float* conc_b = (const float*)d_in[4];
    const float* w1     = (const float*)d_in[5];
    const float* b1     = (const float*)d_in[6];
    const float* w2     = (const float*)d_in[7];
    const float* b2     = (const float*)d_in[8];
    const float* w3     = (const float*)d_in[9];
    const float* b3     = (const float*)d_in[10];
    float* out = (float*)d_out;

    __half *hwh, *hwl, *cwh, *cwl, *w1h, *w1l, *w2h, *w2l;
    __half *chh, *zh, *h1h;
    float* h2;
    cudaGetSymbolAddress((void**)&hwh, g_hwh);
    cudaGetSymbolAddress((void**)&hwl, g_hwl);
    cudaGetSymbolAddress((void**)&cwh, g_cwh);
    cudaGetSymbolAddress((void**)&cwl, g_cwl);
    cudaGetSymbolAddress((void**)&w1h, g_w1h);
    cudaGetSymbolAddress((void**)&w1l, g_w1l);
    cudaGetSymbolAddress((void**)&w2h, g_w2h);
    cudaGetSymbolAddress((void**)&w2l, g_w2l);
    cudaGetSymbolAddress((void**)&chh, g_ch);
    cudaGetSymbolAddress((void**)&zh, g_zh);
    cudaGetSymbolAddress((void**)&h1h, g_h1h);
    cudaGetSymbolAddress((void**)&h2, g_h2);

    cudaFuncSetAttribute(k_heads, cudaFuncAttributeMaxDynamicSharedMemorySize,
                         HEADS_SMEM);
    cudaFuncSetAttribute(k_gemm<0>, cudaFuncAttributeMaxDynamicSharedMemorySize,
                         GEMM_SMEM);
    cudaFuncSetAttribute(k_gemm<1>, cudaFuncAttributeMaxDynamicSharedMemorySize,
                         GEMM_SMEM);
    cudaFuncSetAttribute(k_gemm<2>, cudaFuncAttributeMaxDynamicSharedMemorySize,
                         GEMM_SMEM);

    // order chosen so the ncu capture index lands on a real GEMM:
    // 1 cvt_hw, 2 heads, 3 cvt conc, 4 gemm0 (stage 2), 5 cvt w1,
    // 6 gemm1 (stage 3), 7 cvt w2, 8 gemm2, 9 out
    k_cvt_hw<<<dim3((TOTAL_BINS + 255) / 256, COMP), 256>>>(head_w, hwh, hwl);

    // Stage 1: heads -> combined (hi)
    k_heads<<<dim3(ROWS / 128, N_HEADS), 256, HEADS_SMEM>>>(x, hwh, hwl,
                                                            head_b, chh);

    k_cvt_pad<<<(INPUT_DIM * (INPUT_DIM / 4) + 255) / 256, 256>>>(
        conc_w, cwh, cwl, INPUT_DIM, INPUT_DIM, IN_PAD);
    // Stage 2: z = combined @ conc_w^T + conc_b
    k_gemm<0><<<dim3(BATCH / 128, (INPUT_DIM + 63) / 64), 256, GEMM_SMEM>>>(
        chh, IN_PAD, cwh, cwl, IN_PAD, conc_b, zh, nullptr, IN_PAD,
        INPUT_DIM, INPUT_DIM);

    k_cvt_pad<<<(H1_DIM * (INPUT_DIM / 4) + 255) / 256, 256>>>(
        w1, w1h, w1l, H1_DIM, INPUT_DIM, IN_PAD);
    // Stage 3: h1 = leaky(z @ w1^T + b1)
    k_gemm<1><<<dim3(BATCH / 128, (H1_DIM + 63) / 64), 256, GEMM_SMEM>>>(
        zh, IN_PAD, w1h, w1l, IN_PAD, b1, h1h, nullptr, H1_PAD,
        H1_DIM, INPUT_DIM);

    k_cvt_pad<<<(H2_DIM * (H1_DIM / 4) + 255) / 256, 256>>>(
        w2, w2h, w2l, H2_DIM, H1_DIM, H1_PAD);
    // Stage 4: h2 = leaky(h1 @ w2^T + b2) (fp32 out)
    k_gemm<2><<<dim3(BATCH / 128, 1), 256, GEMM_SMEM>>>(
        h1h, H1_PAD, w2h, w2l, H1_PAD, b2, nullptr, h2, H2_DIM,
        H2_DIM, H1_DIM);
    // Stage 5: out = h2 @ w3^T + b3
    k_out<<<(BATCH * 16 + 255) / 256, 256>>>(h2, w3, b3, out);
}

// round 14
// speedup vs baseline: 2.2270x; 1.2495x over previous
#include <cuda_runtime.h>
#include <cuda_fp16.h>
#include <cstdint>

// ---------------- problem constants ----------------
#define TOTAL_BINS 28749
#define BATCH      2048
#define ROWS       4096
#define INPUT_DIM  2200
#define IN_PAD     2240      // INPUT_DIM padded to 64
#define H1_DIM     1000
#define H1_PAD     1024
#define H2_DIM     50
#define OUT_DIM    13
#define N_HEADS    22
#define COMP       50
#define HW_PAD     29312     // sum of per-segment 64-padded K

__device__ __constant__ int d_LOC[23] = {
    0, 2490, 4912, 6895, 8797, 10612, 12320, 13913, 15364, 16748, 18086,
    19437, 20770, 21914, 22984, 24004, 24907, 25740, 26544, 27130, 27774,
    28241, 28749};
__device__ __constant__ int d_LOC64[23] = {
    0, 2496, 4928, 6912, 8832, 10688, 12416, 14016, 15488, 16896, 18240,
    19648, 20992, 22144, 23232, 24256, 25216, 26112, 26944, 27584, 28288,
    28800, 29312};

// ------- scratch (zero-initialized; pad rows/cols never written) -----
__device__ __half g_hwh[64 * HW_PAD];
__device__ __half g_hwl[64 * HW_PAD];
__device__ __half g_cwh[IN_PAD * IN_PAD];
__device__ __half g_cwl[IN_PAD * IN_PAD];
__device__ __half g_w1h[H1_PAD * IN_PAD];
__device__ __half g_w1l[H1_PAD * IN_PAD];
__device__ __half g_w2h[64 * H1_PAD];
__device__ __half g_w2l[64 * H1_PAD];
__device__ __half g_ch[BATCH * IN_PAD];        // activations: hi only
__device__ __half g_zh[BATCH * IN_PAD];
__device__ __half g_h1h[BATCH * H1_PAD];
__device__ float  g_h2[BATCH * H2_DIM];

// ---------------- smem geometry, pitch 72 f16 = 144 B ----------------
#define PITCH_B   144
// gemm stage: A hi (18432) + W hi (9216) + W lo (9216) = 36864; 3 stages
#define OFF_AH    0
#define OFF_WH    18432
#define OFF_WL    27648
#define ST_STRIDE 36864
#define GEMM_SMEM (3 * ST_STRIDE)        // 110592

// heads: A f16 2 stages (2 x 18432) + W hi/lo 3 stages (3 x 18432)
#define H_AST     18432
#define H_OFFA    0
#define H_OFFW    36864
#define H_WST     18432
#define HEADS_SMEM (36864 + 3 * 18432)   // 92160

__device__ __forceinline__ uint32_t su32(const void* p) {
    uint32_t a;
    asm("{ .reg .u64 t; cvta.to.shared.u64 t, %1; cvt.u32.u64 %0, t; }"
        : "=r"(a) : "l"(p));
    return a;
}

#define CP16(dst, src)                                                        \
    asm volatile("cp.async.cg.shared.global [%0], [%1], 16;" ::"r"(dst),      \
                 "l"(src))
#define CP_COMMIT asm volatile("cp.async.commit_group;" ::: "memory")
#define CP_WAIT1  asm volatile("cp.async.wait_group 1;" ::: "memory")

#define LDSM4(r0, r1, r2, r3, addr)                                          \
    asm volatile(                                                            \
        "ldmatrix.sync.aligned.m8n8.x4.shared.b16 {%0,%1,%2,%3}, [%4];"      \
        : "=r"(r0), "=r"(r1), "=r"(r2), "=r"(r3) : "r"(addr))

__device__ __forceinline__ void mma_f16(float* d, const uint32_t* a,
                                        uint32_t b0, uint32_t b1) {
    asm volatile(
        "mma.sync.aligned.m16n8k16.row.col.f32.f16.f16.f32 "
        "{%0,%1,%2,%3}, {%4,%5,%6,%7}, {%8,%9}, {%0,%1,%2,%3};"
        : "+f"(d[0]), "+f"(d[1]), "+f"(d[2]), "+f"(d[3])
        : "r"(a[0]), "r"(a[1]), "r"(a[2]), "r"(a[3]), "r"(b0), "r"(b1));
}

__device__ __forceinline__ void split_pack(float v0, float v1, uint32_t& hp,
                                           uint32_t& lp) {
    __half2 h = __floats2half2_rn(v0, v1);
    float2 hf = __half22float2(h);
    __half2 l = __floats2half2_rn(v0 - hf.x, v1 - hf.y);
    hp = *(uint32_t*)&h;
    lp = *(uint32_t*)&l;
}
__device__ __forceinline__ uint32_t pack_hi(float v0, float v1) {
    __half2 h = __floats2half2_rn(v0, v1);
    return *(uint32_t*)&h;
}

// =====================================================================
// Weight pre-split: fp32 [N][K] -> f16 hi/lo [N][KP] (pads stay zero)
// =====================================================================
__global__ __launch_bounds__(256) void k_cvt_pad(
    const float* __restrict__ src, __half* __restrict__ dh,
    __half* __restrict__ dl, int N, int K, int KP) {
    const int k4 = K >> 2;
    const int i4 = blockIdx.x * 256 + threadIdx.x;
    if (i4 >= N * k4) return;
    const int row = i4 / k4, col = (i4 - row * k4) * 4;
    const float4 v = *(const float4*)(src + (size_t)row * K + col);
    uint32_t h0, l0, h1, l1;
    split_pack(v.x, v.y, h0, l0);
    split_pack(v.z, v.w, h1, l1);
    const size_t o = (size_t)row * KP + col;
    *(uint2*)(dh + o) = make_uint2(h0, h1);
    *(uint2*)(dl + o) = make_uint2(l0, l1);
}

// head_w fp32 [50][28749] -> padded [64][HW_PAD] hi/lo (per-seg 64-aligned)
__global__ __launch_bounds__(256) void k_cvt_hw(
    const float* __restrict__ hw, __half* __restrict__ dh,
    __half* __restrict__ dl) {
    const int o = blockIdx.y;
    const int kp = blockIdx.x * 256 + threadIdx.x;
    if (kp >= TOTAL_BINS) return;
    int seg = 0;
#pragma unroll
    for (int s = 1; s < 22; s++) seg += (kp >= d_LOC[s]);
    const float v = hw[(size_t)o * TOTAL_BINS + kp];
    const __half h = __float2half_rn(v);
    const size_t off = (size_t)o * HW_PAD + d_LOC64[seg] + (kp - d_LOC[seg]);
    dh[off] = h;
    dl[off] = __float2half_rn(v - __half2float(h));
}

// =====================================================================
// Heads: x fp32 -> LDG to regs (chunk s+1 prefetched during mma of s)
// -> pack f16 hi -> STS. W f16 hi/lo via 3-stage cp.async.
// One __syncthreads per chunk. Tile 128 x 64(=50), K-chunk 64, 256 thr.
// =====================================================================
__global__ __launch_bounds__(256, 2) void k_heads(
    const float* __restrict__ x, const __half* __restrict__ hwh,
    const __half* __restrict__ hwl, const float* __restrict__ hb,
    __half* __restrict__ ch) {
    extern __shared__ __align__(16) char smem[];
    const uint32_t sb = su32(smem);
    const int tid = threadIdx.x, lane = tid & 31, wid = tid >> 5;
    const int wm = wid & 3, wn = wid >> 2;
    const int m0 = blockIdx.x * 128, seg = blockIdx.y;
    const int a = d_LOC[seg], Ks = d_LOC[seg + 1] - a;
    const int kb = d_LOC64[seg];
    const int nch = (d_LOC64[seg + 1] - kb) >> 6;
    const float* bias = hb + seg * COMP;

    float acc[2][4][4] = {};
    const uint32_t a_row = (uint32_t)(wm * 32 + (lane & 15));
    const uint32_t a_cb = (uint32_t)((lane >> 4) << 4);
    const uint32_t w_row = (uint32_t)(wn * 32 + ((lane >> 4) << 3) + (lane & 7));
    const uint32_t w_cb = (uint32_t)((lane & 8) * 2);

    // this thread's fixed (row, kp) slots: idx = i*256+tid
    const int xrow = tid >> 5;         // base row group: rows xrow + 8*i
    const int xkp = tid & 31;          // k-pair index

    float xv[32];
    auto ldx = [&](int ck) {
        const int k0 = ck << 6;
        const int k = k0 + xkp * 2;
        const bool full = (k0 + 64 <= Ks);
        if (full) {
#pragma unroll
            for (int i = 0; i < 16; i++) {
                const float* ap =
                    x + (size_t)(m0 + xrow + i * 8) * TOTAL_BINS + a + k;
                xv[2 * i] = ap[0];
                xv[2 * i + 1] = ap[1];
            }
        } else {
            const bool g0 = k < Ks, g1 = k + 1 < Ks;
#pragma unroll
            for (int i = 0; i < 16; i++) {
                const float* ap =
                    x + (size_t)(m0 + xrow + i * 8) * TOTAL_BINS + a + k;
                xv[2 * i] = g0 ? ap[0] : 0.f;
                xv[2 * i + 1] = g1 ? ap[1] : 0.f;
            }
        }
    };
    auto stx = [&](int s) {
        const uint32_t base = (uint32_t)(xrow * PITCH_B + xkp * 4) + s * H_AST;
#pragma unroll
        for (int i = 0; i < 16; i++)
            *(uint32_t*)(smem + H_OFFA + base + i * 8 * PITCH_B) =
                pack_hi(xv[2 * i], xv[2 * i + 1]);
    };
    auto load_w = [&](int ck, int s) {
        const int k0 = ck << 6;
#pragma unroll
        for (int i = 0; i < 2; i++) {
            const int idx = i * 256 + tid;
            const int row = idx >> 3, p = idx & 7;
            const size_t so = (size_t)row * HW_PAD + kb + k0 + p * 8;
            const uint32_t dst =
                sb + H_OFFW + s * H_WST + row * PITCH_B + p * 16;
            CP16(dst, hwh + so);
            CP16(dst + 9216, hwl + so);
        }
    };

    // prologue: A chunk0 regs->smem, W stages 0,1
    ldx(0);
    load_w(0, 0);
    CP_COMMIT;
    if (1 < nch) load_w(1, 1);
    CP_COMMIT;
    stx(0);

    int s2 = 0, s3 = 0;
    for (int ck = 0; ck < nch; ck++) {
        CP_WAIT1;
        __syncthreads();   // A buf s2 + W buf s3 ready for all warps

        int s3n = s3 + 2;
        if (s3n >= 3) s3n -= 3;
        if (ck + 2 < nch) load_w(ck + 2, s3n);
        CP_COMMIT;
        if (ck + 1 < nch) ldx(ck + 1);   // LDG latency hidden by mma below

        const uint32_t abase = sb + H_OFFA + s2 * H_AST;
        const uint32_t wbase = sb + H_OFFW + s3 * H_WST;
#pragma unroll
        for (int ks = 0; ks < 4; ks++) {
            uint32_t ah[2][4], wh[4][2], wl[4][2];
#pragma unroll
            for (int mt = 0; mt < 2; mt++) {
                const uint32_t ro = (a_row + mt * 16) * PITCH_B + ks * 32 + a_cb;
                LDSM4(ah[mt][0], ah[mt][1], ah[mt][2], ah[mt][3], abase + ro);
            }
#pragma unroll
            for (int p = 0; p < 2; p++) {
                const uint32_t ro = (w_row + p * 16) * PITCH_B + ks * 32 + w_cb;
                LDSM4(wh[2 * p][0], wh[2 * p][1], wh[2 * p + 1][0],
                      wh[2 * p + 1][1], wbase + ro);
                LDSM4(wl[2 * p][0], wl[2 * p][1], wl[2 * p + 1][0],
                      wl[2 * p + 1][1], wbase + 9216 + ro);
            }
#pragma unroll
            for (int mt = 0; mt < 2; mt++)
#pragma unroll
                for (int nt = 0; nt < 4; nt++) {
                    mma_f16(acc[mt][nt], ah[mt], wh[nt][0], wh[nt][1]);
                    mma_f16(acc[mt][nt], ah[mt], wl[nt][0], wl[nt][1]);
                }
        }
        if (ck + 1 < nch) stx(s2 ^ 1);
        s2 ^= 1;
        s3 = (s3 + 1 == 3) ? 0 : s3 + 1;
    }

    // epilogue: pack hi, scatter to combined
#pragma unroll
    for (int mt = 0; mt < 2; mt++) {
        const int rowl = wm * 32 + mt * 16 + (lane >> 2);
#pragma unroll
        for (int nt = 0; nt < 4; nt++) {
            const int col = wn * 32 + nt * 8 + 2 * (lane & 3);
            if (col >= COMP) continue;
            const float b0 = bias[col], b1 = bias[col + 1];
#pragma unroll
            for (int h = 0; h < 2; h++) {
                const int r = m0 + rowl + h * 8;
                const int b = r >> 1, c = r & 1;
                const size_t o = (size_t)b * IN_PAD + seg * 100 + c * COMP + col;
                *(uint32_t*)(ch + o) =
                    pack_hi(acc[mt][nt][2 * h] + b0, acc[mt][nt][2 * h + 1] + b1);
            }
        }
    }
}

// =====================================================================
// GEMM: A f16 hi, W f16 hi/lo (2 products), 3-stage cp.async pipeline,
// one __syncthreads per chunk.
// EPI: 0 = plain -> hi out, 1 = leaky -> hi out, 2 = leaky -> fp32
// =====================================================================
template <int EPI>
__global__ __launch_bounds__(256, 2) void k_gemm(
    const __half* __restrict__ Ah, int lda, const __half* __restrict__ Wh,
    const __half* __restrict__ Wl, int ldw, const float* __restrict__ bias,
    __half* __restrict__ Ch, float* __restrict__ Cf, int ldc, int N, int K) {
    extern __shared__ __align__(16) char smem[];
    const uint32_t sb = su32(smem);
    const int tid = threadIdx.x, lane = tid & 31, wid = tid >> 5;
    const int wm = wid & 3, wn = wid >> 2;
    const int m0 = blockIdx.x * 128, n0 = blockIdx.y * 64;
    const int nv = (N - n0 < 64) ? (N - n0) : 64;

    float acc[2][4][4] = {};
    const uint32_t a_row = (uint32_t)(wm * 32 + (lane & 15));
    const uint32_t a_cb = (uint32_t)((lane >> 4) << 4);
    const uint32_t w_row = (uint32_t)(wn * 32 + ((lane >> 4) << 3) + (lane & 7));
    const uint32_t w_cb = (uint32_t)((lane & 8) * 2);

    auto load_chunk = [&](int ck, int s) {
        const int k0 = ck << 6;
        const uint32_t sbase = sb + s * ST_STRIDE;
#pragma unroll
        for (int i = 0; i < 4; i++) {
            const int idx = i * 256 + tid;
            const int row = idx >> 3, p = idx & 7;
            const size_t so = (size_t)(m0 + row) * lda + k0 + p * 8;
            CP16(sbase + OFF_AH + row * PITCH_B + p * 16, Ah + so);
        }
#pragma unroll
        for (int i = 0; i < 2; i++) {
            const int idx = i * 256 + tid;
            const int row = idx >> 3, p = idx & 7;
            const size_t so = (size_t)(n0 + row) * ldw + k0 + p * 8;
            const uint32_t o = sbase + row * PITCH_B + p * 16;
            CP16(o + OFF_WH, Wh + so);
            CP16(o + OFF_WL, Wl + so);
        }
    };

    const int nch = (K + 63) >> 6;
    load_chunk(0, 0);
    CP_COMMIT;
    load_chunk(1, 1);
    CP_COMMIT;

    int s = 0;
    for (int ck = 0; ck < nch; ck++) {
        CP_WAIT1;
        __syncthreads();

        int s2 = s + 2;
        if (s2 >= 3) s2 -= 3;
        if (ck + 2 < nch) load_chunk(ck + 2, s2);
        CP_COMMIT;

        const uint32_t sbase = sb + s * ST_STRIDE;
#pragma unroll
        for (int ks = 0; ks < 4; ks++) {
            uint32_t ah[2][4], wh[4][2], wl[4][2];
#pragma unroll
            for (int mt = 0; mt < 2; mt++) {
                const uint32_t ro = (a_row + mt * 16) * PITCH_B + ks * 32 + a_cb;
                LDSM4(ah[mt][0], ah[mt][1], ah[mt][2], ah[mt][3],
                      sbase + OFF_AH + ro);
            }
#pragma unroll
            for (int p = 0; p < 2; p++) {
                const uint32_t ro = (w_row + p * 16) * PITCH_B + ks * 32 + w_cb;
                LDSM4(wh[2 * p][0], wh[2 * p][1], wh[2 * p + 1][0],
                      wh[2 * p + 1][1], sbase + OFF_WH + ro);
                LDSM4(wl[2 * p][0], wl[2 * p][1], wl[2 * p + 1][0],
                      wl[2 * p + 1][1], sbase + OFF_WL + ro);
            }
#pragma unroll
            for (int mt = 0; mt < 2; mt++)
#pragma unroll
                for (int nt = 0; nt < 4; nt++) {
                    mma_f16(acc[mt][nt], ah[mt], wh[nt][0], wh[nt][1]);
                    mma_f16(acc[mt][nt], ah[mt], wl[nt][0], wl[nt][1]);
                }
        }
        s = (s + 1 == 3) ? 0 : s + 1;
    }

#pragma unroll
    for (int mt = 0; mt < 2; mt++) {
        const int rowl = wm * 32 + mt * 16 + (lane >> 2);
#pragma unroll
        for (int nt = 0; nt < 4; nt++) {
            const int col = wn * 32 + nt * 8 + 2 * (lane & 3);
            if (col >= nv) continue;
            const int n = n0 + col;
            const float b0 = bias[n], b1 = bias[n + 1];
#pragma unroll
            for (int h = 0; h < 2; h++) {
                float v0 = acc[mt][nt][2 * h] + b0;
                float v1 = acc[mt][nt][2 * h + 1] + b1;
                if (EPI >= 1) {
                    v0 = v0 > 0.f ? v0 : 0.01f * v0;
                    v1 = v1 > 0.f ? v1 : 0.01f * v1;
                }
                const size_t o = (size_t)(m0 + rowl + h * 8) * ldc + n;
                if (EPI == 2)
                    *(float2*)(Cf + o) = make_float2(v0, v1);
                else
                    *(uint32_t*)(Ch + o) = pack_hi(v0, v1);
            }
        }
    }
}

// final 50 -> 13 layer, fp32
__global__ __launch_bounds__(256) void k_out(
    const float* __restrict__ h2, const float* __restrict__ w3,
    const float* __restrict__ b3, float* __restrict__ out) {
    const int gid = blockIdx.x * 256 + threadIdx.x;
    const int m = gid >> 4, j = gid & 15;
    if (m < BATCH && j < OUT_DIM) {
        float acc = b3[j];
        const float* hr = h2 + (size_t)m * H2_DIM;
        const float* wr = w3 + j * H2_DIM;
#pragma unroll
        for (int k = 0; k < H2_DIM; k++) acc += hr[k] * wr[k];
        out[(size_t)m * OUT_DIM + j] = acc;
    }
}

// =====================================================================
extern "C" void kernel_launch(void* const* d_in, const int* in_sizes, int n_in,
                              void* d_out, int out_size) {
    const float* x      = (const float*)d_in[0];
    const float* head_w = (const float*)d_in[1];
    const float* head_b = (const float*)d_in[2];
    const float* conc_w = (const float*)d_in[3];
    const float* conc_b = (const float*)d_in[4];
    const float* w1     = (const float*)d_in[5];
    const float* b1     = (const float*)d_in[6];
    const float* w2     = (const float*)d_in[7];
    const float* b2     = (const float*)d_in[8];
    const float* w3     = (const float*)d_in[9];
    const float* b3     = (const float*)d_in[10];
    float* out = (float*)d_out;

    __half *hwh, *hwl, *cwh, *cwl, *w1h, *w1l, *w2h, *w2l;
    __half *chh, *zh, *h1h;
    float* h2;
    cudaGetSymbolAddress((void**)&hwh, g_hwh);
    cudaGetSymbolAddress((void**)&hwl, g_hwl);
    cudaGetSymbolAddress((void**)&cwh, g_cwh);
    cudaGetSymbolAddress((void**)&cwl, g_cwl);
    cudaGetSymbolAddress((void**)&w1h, g_w1h);
    cudaGetSymbolAddress((void**)&w1l, g_w1l);
    cudaGetSymbolAddress((void**)&w2h, g_w2h);
    cudaGetSymbolAddress((void**)&w2l, g_w2l);
    cudaGetSymbolAddress((void**)&chh, g_ch);
    cudaGetSymbolAddress((void**)&zh, g_zh);
    cudaGetSymbolAddress((void**)&h1h, g_h1h);
    cudaGetSymbolAddress((void**)&h2, g_h2);

    cudaFuncSetAttribute(k_heads, cudaFuncAttributeMaxDynamicSharedMemorySize,
                         HEADS_SMEM);
    cudaFuncSetAttribute(k_gemm<0>, cudaFuncAttributeMaxDynamicSharedMemorySize,
                         GEMM_SMEM);
    cudaFuncSetAttribute(k_gemm<1>, cudaFuncAttributeMaxDynamicSharedMemorySize,
                         GEMM_SMEM);
    cudaFuncSetAttribute(k_gemm<2>, cudaFuncAttributeMaxDynamicSharedMemorySize,
                         GEMM_SMEM);

    // same launch order as R13 so profiles stay comparable
    k_cvt_hw<<<dim3((TOTAL_BINS + 255) / 256, COMP), 256>>>(head_w, hwh, hwl);

    // Stage 1: heads -> combined (hi)
    k_heads<<<dim3(ROWS / 128, N_HEADS), 256, HEADS_SMEM>>>(x, hwh, hwl,
                                                            head_b, chh);

    k_cvt_pad<<<(INPUT_DIM * (INPUT_DIM / 4) + 255) / 256, 256>>>(
        conc_w, cwh, cwl, INPUT_DIM, INPUT_DIM, IN_PAD);
    // Stage 2: z = combined @ conc_w^T + conc_b
    k_gemm<0><<<dim3(BATCH / 128, (INPUT_DIM + 63) / 64), 256, GEMM_SMEM>>>(
        chh, IN_PAD, cwh, cwl, IN_PAD, conc_b, zh, nullptr, IN_PAD,
        INPUT_DIM, INPUT_DIM);

    k_cvt_pad<<<(H1_DIM * (INPUT_DIM / 4) + 255) / 256, 256>>>(
        w1, w1h, w1l, H1_DIM, INPUT_DIM, IN_PAD);
    // Stage 3: h1 = leaky(z @ w1^T + b1)
    k_gemm<1><<<dim3(BATCH / 128, (H1_DIM + 63) / 64), 256, GEMM_SMEM>>>(
        zh, IN_PAD, w1h, w1l, IN_PAD, b1, h1h, nullptr, H1_PAD,
        H1_DIM, INPUT_DIM);

    k_cvt_pad<<<(H2_DIM * (H1_DIM / 4) + 255) / 256, 256>>>(
        w2, w2h, w2l, H2_DIM, H1_DIM, H1_PAD);
    // Stage 4: h2 = leaky(h1 @ w2^T + b2) (fp32 out)
    k_gemm<2><<<dim3(BATCH / 128, 1), 256, GEMM_SMEM>>>(
        h1h, H1_PAD, w2h, w2l, H1_PAD, b2, nullptr, h2, H2_DIM,
        H2_DIM, H1_DIM);
    // Stage 5: out = h2 @ w3^T + b3
    k_out<<<(BATCH * 16 + 255) / 256, 256>>>(h2, w3, b3, out);
}